// round 1
// baseline (speedup 1.0000x reference)
#include <cuda_runtime.h>
#include <math.h>

#define Bb 16
#define Hh 512
#define Ll 4096
#define NC 4096            // complex FFT length (packed real FFT of 8192)
#define LOG2NC 12
#define LAMBDA 0.001f

// Scratch: static device globals (no runtime allocation allowed)
__device__ float2 g_Kf[Hh * (NC + 1)];                 // kernel rfft spectrum, scaled by 1/NC
__device__ float  g_Yact[(size_t)Bb * Hh * Ll];        // gelu(conv + skip), GEMM input

__device__ __forceinline__ float2 cmul(float2 a, float2 b) {
    return make_float2(a.x * b.x - a.y * b.y, a.x * b.y + a.y * b.x);
}
__device__ __forceinline__ float2 cadd(float2 a, float2 b) { return make_float2(a.x + b.x, a.y + b.y); }
__device__ __forceinline__ float2 csub(float2 a, float2 b) { return make_float2(a.x - b.x, a.y - b.y); }
__device__ __forceinline__ float2 conjf2(float2 a) { return make_float2(a.x, -a.y); }
__device__ __forceinline__ float2 cscale(float2 a, float s) { return make_float2(a.x * s, a.y * s); }

// In-place radix-2 DIT FFT of NC complex points in shared memory.
// tw[j] = exp(-2*pi*i*j/NC), j in [0, NC/2)
__device__ void fft_shared(float2* z, const float2* tw, int tid, bool inverse) {
    // bit-reversal permutation
    for (int n = tid; n < NC; n += blockDim.x) {
        int r = __brev(n) >> (32 - LOG2NC);
        if (r > n) { float2 t = z[n]; z[n] = z[r]; z[r] = t; }
    }
    __syncthreads();
    for (int s = 1; s <= LOG2NC; s++) {
        int half  = 1 << (s - 1);
        int tstep = NC >> s;
        for (int t = tid; t < NC / 2; t += blockDim.x) {
            int j  = t & (half - 1);
            int i0 = ((t >> (s - 1)) << s) + j;
            int i1 = i0 + half;
            float2 w = tw[j * tstep];
            if (inverse) w.y = -w.y;
            float2 bb = cmul(w, z[i1]);
            float2 a  = z[i0];
            z[i0] = cadd(a, bb);
            z[i1] = csub(a, bb);
        }
        __syncthreads();
    }
}

__device__ __forceinline__ void fill_twiddles(float2* tw, int tid) {
    for (int j = tid; j < NC / 2; j += blockDim.x) {
        float sv, cv;
        sincosf(-2.0f * (float)M_PI * (float)j / (float)NC, &sv, &cv);
        tw[j] = make_float2(cv, sv);
    }
}

// ---------------------------------------------------------------------------
// Kernel A: squash kernel params, rfft(8192) via packed 4096-pt complex FFT,
// unpack to full half-spectrum [0..NC], fold 1/NC IFFT scale into spectrum.
// ---------------------------------------------------------------------------
__global__ void build_kf_kernel(const float* __restrict__ kparam) {
    extern __shared__ float2 sh[];
    float2* z  = sh;           // NC complex
    float2* tw = sh + NC;      // NC/2 complex
    int tid = threadIdx.x;
    int h   = blockIdx.x;

    fill_twiddles(tw, tid);

    const float* kp = kparam + (size_t)h * Ll;
    for (int n = tid; n < NC; n += blockDim.x) {
        float a = 0.f, b = 0.f;
        if (n < NC / 2) {
            float k0 = kp[2 * n], k1 = kp[2 * n + 1];
            float s0 = fabsf(k0) - LAMBDA; a = (s0 > 0.f) ? copysignf(s0, k0) : 0.f;
            float s1 = fabsf(k1) - LAMBDA; b = (s1 > 0.f) ? copysignf(s1, k1) : 0.f;
        }
        z[n] = make_float2(a, b);
    }
    __syncthreads();

    fft_shared(z, tw, tid, false);

    float2* out = g_Kf + (size_t)h * (NC + 1);
    const float scale = 1.0f / (float)NC;   // IFFT normalization folded here
    for (int k = tid; k <= NC / 2; k += blockDim.x) {
        if (k == 0) {
            float2 Z0 = z[0];
            out[0]  = make_float2((Z0.x + Z0.y) * scale, 0.f);
            out[NC] = make_float2((Z0.x - Z0.y) * scale, 0.f);
        } else if (k == NC / 2) {
            float2 Zm = z[NC / 2];
            out[NC / 2] = make_float2(Zm.x * scale, -Zm.y * scale);   // conj(Z[NC/2])
        } else {
            int j = NC - k;
            float2 Zk = z[k], Zj = z[j];
            float2 E = make_float2(0.5f * (Zk.x + Zj.x),  0.5f * (Zk.y - Zj.y));
            float2 O = make_float2(0.5f * (Zk.y + Zj.y), -0.5f * (Zk.x - Zj.x));
            float sv, cv;
            sincosf(-(float)M_PI * (float)k / (float)NC, &sv, &cv);
            float2 W  = make_float2(cv, sv);          // W_8192^k
            float2 Wj = make_float2(-cv, sv);         // W_8192^(NC-k) = -conj(W)
            float2 Xk = cadd(E, cmul(W, O));
            float2 Xj = cadd(conjf2(E), cmul(Wj, conjf2(O)));
            out[k] = cscale(Xk, scale);
            out[j] = cscale(Xj, scale);
        }
    }
}

// ---------------------------------------------------------------------------
// Kernel B: per (b,h): rfft(u) -> multiply by Kf -> irfft -> + D*u -> exact GELU
// All via packed real FFT, one CTA per (b,h), everything in shared memory.
// ---------------------------------------------------------------------------
__global__ void conv_kernel(const float* __restrict__ u, const float* __restrict__ D) {
    extern __shared__ float2 sh[];
    float2* z  = sh;
    float2* tw = sh + NC;
    int tid = threadIdx.x;
    int h = blockIdx.x, b = blockIdx.y;

    fill_twiddles(tw, tid);

    const float* up = u + ((size_t)(b * Hh + h)) * Ll;
    for (int n = tid; n < NC; n += blockDim.x) {
        float a = 0.f, bb = 0.f;
        if (n < NC / 2) { a = up[2 * n]; bb = up[2 * n + 1]; }
        z[n] = make_float2(a, bb);
    }
    __syncthreads();

    fft_shared(z, tw, tid, false);   // Z = FFT of packed u

    const float2* Kf = g_Kf + (size_t)h * (NC + 1);
    // unpack -> multiply -> repack (pairs (k, NC-k) owned by one thread -> race-free)
    for (int k = tid; k <= NC / 2; k += blockDim.x) {
        if (k == 0) {
            float2 Z0 = z[0];
            float U0 = Z0.x + Z0.y;     // U[0]  (real)
            float UN = Z0.x - Z0.y;     // U[NC] (real)
            float2 Y0 = cscale(Kf[0], U0);
            float2 YN = cscale(Kf[NC], UN);
            float2 Ey = make_float2(0.5f * (Y0.x + YN.x), 0.5f * (Y0.y - YN.y)); // 0.5*(Y0+conj(YN))
            float2 Oy = make_float2(0.5f * (Y0.x - YN.x), 0.5f * (Y0.y + YN.y)); // 0.5*(Y0-conj(YN))
            z[0] = make_float2(Ey.x - Oy.y, Ey.y + Oy.x);                         // Ey + i*Oy
        } else if (k == NC / 2) {
            float2 Zm = z[NC / 2];
            float2 Y  = cmul(conjf2(Zm), Kf[NC / 2]);   // U[NC/2] = conj(Z[NC/2])
            z[NC / 2] = conjf2(Y);                       // Zy[NC/2] = conj(Y)
        } else {
            int j = NC - k;
            float2 Zk = z[k], Zj = z[j];
            float2 E = make_float2(0.5f * (Zk.x + Zj.x),  0.5f * (Zk.y - Zj.y));
            float2 O = make_float2(0.5f * (Zk.y + Zj.y), -0.5f * (Zk.x - Zj.x));
            float sv, cv;
            sincosf(-(float)M_PI * (float)k / (float)NC, &sv, &cv);
            float2 W  = make_float2(cv, sv);     // W_8192^k
            float2 Wj = make_float2(-cv, sv);    // -conj(W)
            float2 Uk = cadd(E, cmul(W, O));
            float2 Uj = cadd(conjf2(E), cmul(Wj, conjf2(O)));
            float2 Yk = cmul(Uk, Kf[k]);
            float2 Yj = cmul(Uj, Kf[j]);
            // repack: Zy[k] = Ey + i*Wc*T ; Zy[j] = conj(Ey) + i*W*conj(T)
            float2 Ey = make_float2(0.5f * (Yk.x + Yj.x), 0.5f * (Yk.y - Yj.y));
            float2 T  = make_float2(0.5f * (Yk.x - Yj.x), 0.5f * (Yk.y + Yj.y));
            float2 Oy  = cmul(conjf2(W), T);
            float2 OyJ = cmul(W, conjf2(T));
            z[k] = make_float2(Ey.x - Oy.y,   Ey.y + Oy.x);
            z[j] = make_float2(Ey.x - OyJ.y, -Ey.y + OyJ.x);
        }
    }
    __syncthreads();

    fft_shared(z, tw, tid, true);    // inverse (scale already folded into Kf)

    float dcoef = D[h];
    float* yout = g_Yact + ((size_t)(b * Hh + h)) * Ll;
    const float INV_SQRT2 = 0.70710678118654752f;
    for (int n = tid; n < NC / 2; n += blockDim.x) {
        float2 zy = z[n];
        float y0 = zy.x + dcoef * up[2 * n];
        float y1 = zy.y + dcoef * up[2 * n + 1];
        y0 = 0.5f * y0 * (1.0f + erff(y0 * INV_SQRT2));   // exact GELU
        y1 = 0.5f * y1 * (1.0f + erff(y1 * INV_SQRT2));
        yout[2 * n]     = y0;
        yout[2 * n + 1] = y1;
    }
}

// ---------------------------------------------------------------------------
// Kernel C: out[b,v,l] = silu( sum_u Wout[v,u] * Yact[b,u,l] + bout[v] )
// fp32 tiled GEMM: BM=128 x BN=64 x BK=16, 256 threads, 8x4 per-thread tile.
// ---------------------------------------------------------------------------
#define BM 128
#define BN 64
#define BK 16

__global__ __launch_bounds__(256) void gemm_silu_kernel(
    const float* __restrict__ W, const float* __restrict__ bias,
    float* __restrict__ out)
{
    __shared__ float As[BK][BM];
    __shared__ float Bs[BK][BN];
    int tid = threadIdx.x;
    int nb = blockIdx.x;         // 0..63  (l tiles)
    int mb = blockIdx.y;         // 0..3   (v tiles)
    int b  = blockIdx.z;         // 0..15  (batch)
    int l0 = nb * BN, v0 = mb * BM;
    const float* Y = g_Yact + (size_t)b * Hh * Ll;

    float acc[8][4];
#pragma unroll
    for (int i = 0; i < 8; i++)
#pragma unroll
        for (int j = 0; j < 4; j++) acc[i][j] = 0.f;

    int tm = tid >> 4;   // 0..15 -> 8 rows each
    int tn = tid & 15;   // 0..15 -> 4 cols each

    for (int k0 = 0; k0 < Hh; k0 += BK) {
        // A tile: W[v0..v0+127][k0..k0+15] stored transposed into As[k][m]
#pragma unroll
        for (int i = 0; i < 2; i++) {
            int f   = tid + 256 * i;
            int row = f >> 2;     // 0..127
            int c4  = f & 3;      // 0..3
            float4 w4 = *(const float4*)(W + (size_t)(v0 + row) * Hh + k0 + c4 * 4);
            As[c4 * 4 + 0][row] = w4.x;
            As[c4 * 4 + 1][row] = w4.y;
            As[c4 * 4 + 2][row] = w4.z;
            As[c4 * 4 + 3][row] = w4.w;
        }
        // B tile: Y[k0..k0+15][l0..l0+63]
        {
            int r  = tid >> 4;    // 0..15
            int c4 = tid & 15;    // 0..15
            float4 y4 = *(const float4*)(Y + (size_t)(k0 + r) * Ll + l0 + c4 * 4);
            *(float4*)&Bs[r][c4 * 4] = y4;
        }
        __syncthreads();

#pragma unroll
        for (int kk = 0; kk < BK; kk++) {
            float a[8], bb[4];
#pragma unroll
            for (int i = 0; i < 8; i++) a[i] = As[kk][tm * 8 + i];
#pragma unroll
            for (int j = 0; j < 4; j++) bb[j] = Bs[kk][tn * 4 + j];
#pragma unroll
            for (int i = 0; i < 8; i++)
#pragma unroll
                for (int j = 0; j < 4; j++)
                    acc[i][j] = fmaf(a[i], bb[j], acc[i][j]);
        }
        __syncthreads();
    }

#pragma unroll
    for (int i = 0; i < 8; i++) {
        int v = v0 + tm * 8 + i;
        float bv = bias[v];
        float x0 = acc[i][0] + bv;
        float x1 = acc[i][1] + bv;
        float x2 = acc[i][2] + bv;
        float x3 = acc[i][3] + bv;
        float4 r;
        r.x = x0 / (1.f + expf(-x0));
        r.y = x1 / (1.f + expf(-x1));
        r.z = x2 / (1.f + expf(-x2));
        r.w = x3 / (1.f + expf(-x3));
        float* op = out + ((size_t)(b * Hh + v)) * Ll + l0 + tn * 4;
        *(float4*)op = r;
    }
}

extern "C" void kernel_launch(void* const* d_in, const int* in_sizes, int n_in,
                              void* d_out, int out_size) {
    const float* u    = (const float*)d_in[0];   // (16, 512, 4096)
    const float* kern = (const float*)d_in[1];   // (1, 512, 4096)
    const float* D    = (const float*)d_in[2];   // (1, 512)
    const float* Wout = (const float*)d_in[3];   // (512, 512)
    const float* bout = (const float*)d_in[4];   // (512,)
    float* out = (float*)d_out;                  // (16, 512, 4096)

    size_t shmem = (size_t)(NC + NC / 2) * sizeof(float2);   // 49152 B (== 48KB limit)

    build_kf_kernel<<<Hh, 512, shmem>>>(kern);
    conv_kernel<<<dim3(Hh, Bb), 512, shmem>>>(u, D);
    gemm_silu_kernel<<<dim3(Ll / BN, Hh / BM, Bb), 256>>>(Wout, bout, out);
}

// round 2
// speedup vs baseline: 1.7302x; 1.7302x over previous
#include <cuda_runtime.h>
#include <math.h>

#define Bb 16
#define Hh 512
#define Ll 4096
#define NC 4096
#define LAMBDA 0.001f

// Scratch (no runtime allocation allowed)
__device__ float2 g_Kf[Hh * (NC + 1)];            // kernel spectrum, 1/NC folded in
__device__ float  g_Yact[(size_t)Bb * Hh * Ll];   // gelu(conv + skip), GEMM input

__device__ __forceinline__ float2 cadd(float2 a, float2 b) { return make_float2(a.x + b.x, a.y + b.y); }
__device__ __forceinline__ float2 csub(float2 a, float2 b) { return make_float2(a.x - b.x, a.y - b.y); }
__device__ __forceinline__ float2 cmul(float2 a, float2 b) {
    return make_float2(a.x * b.x - a.y * b.y, a.x * b.y + a.y * b.x);
}
__device__ __forceinline__ float2 conjf2(float2 a) { return make_float2(a.x, -a.y); }
__device__ __forceinline__ float2 cscale(float2 a, float s) { return make_float2(a.x * s, a.y * s); }

// padded smem index: breaks power-of-2 stride conflicts (<=2-way everywhere)
__device__ __forceinline__ int sidx(int n) { return n + (n >> 4); }
#define SMSZ (4096 + 256)

// ---------------------------------------------------------------------------
// radix-8 butterfly (DIT). INV flips all rotation signs.
// ---------------------------------------------------------------------------
template <bool INV>
__device__ __forceinline__ void radix8(float2 a[8]) {
    const float C = 0.70710678118654752440f;
    float2 t0 = cadd(a[0], a[4]);
    float2 t1 = csub(a[0], a[4]);
    float2 t2 = cadd(a[2], a[6]);
    float2 t3;
    { float2 d = csub(a[2], a[6]); t3 = INV ? make_float2(-d.y, d.x) : make_float2(d.y, -d.x); }
    float2 E0 = cadd(t0, t2), E2 = csub(t0, t2);
    float2 E1 = cadd(t1, t3), E3 = csub(t1, t3);
    float2 s0 = cadd(a[1], a[5]);
    float2 s1 = csub(a[1], a[5]);
    float2 s2 = cadd(a[3], a[7]);
    float2 s3;
    { float2 d = csub(a[3], a[7]); s3 = INV ? make_float2(-d.y, d.x) : make_float2(d.y, -d.x); }
    float2 O0 = cadd(s0, s2), O2 = csub(s0, s2);
    float2 O1 = cadd(s1, s3), O3 = csub(s1, s3);
    float2 O1w, O2w, O3w;
    if (!INV) {
        O1w = make_float2(C * (O1.x + O1.y), C * (O1.y - O1.x));    // * W8^1 = (c,-c)
        O2w = make_float2(O2.y, -O2.x);                              // * -i
        O3w = make_float2(C * (O3.y - O3.x), -C * (O3.x + O3.y));    // * W8^3 = (-c,-c)
    } else {
        O1w = make_float2(C * (O1.x - O1.y), C * (O1.y + O1.x));     // * (c,c)
        O2w = make_float2(-O2.y, O2.x);                              // * +i
        O3w = make_float2(-C * (O3.x + O3.y), C * (O3.x - O3.y));    // * (-c,c)
    }
    a[0] = cadd(E0, O0);  a[4] = csub(E0, O0);
    a[1] = cadd(E1, O1w); a[5] = csub(E1, O1w);
    a[2] = cadd(E2, O2w); a[6] = csub(E2, O2w);
    a[3] = cadd(E3, O3w); a[7] = csub(E3, O3w);
}

// stage 0: gather digit-reversed positions from natural-order array, butterfly,
// scatter to natural in-place layout. read->sync->write (whole-array rotation).
template <bool INV>
__device__ __forceinline__ void stage0(float* re, float* im, int t) {
    int r3 = ((t & 7) << 6) | (t & 56) | (t >> 6);   // octal-digit reversal of t
    float2 a[8];
#pragma unroll
    for (int i = 0; i < 8; i++) { int p = sidx(i * 512 + r3); a[i] = make_float2(re[p], im[p]); }
    __syncthreads();
    radix8<INV>(a);
#pragma unroll
    for (int i = 0; i < 8; i++) { int p = sidx(8 * t + i); re[p] = a[i].x; im[p] = a[i].y; }
}

// generic stage S in {1,2,3}: in-place on thread-private slot set
template <bool INV, int S>
__device__ __forceinline__ void stage(float* re, float* im, int t) {
    constexpr int ST = 1 << (3 * S);
    constexpr int M8 = ST * 8;
    int j = t & (ST - 1);
    int base = ((t >> (3 * S)) << (3 * (S + 1))) + j;
    float2 a[8];
#pragma unroll
    for (int i = 0; i < 8; i++) { int p = sidx(base + i * ST); a[i] = make_float2(re[p], im[p]); }
    if (j) {
        float ang = (INV ? 6.283185307179586f : -6.283185307179586f) * (float)j / (float)M8;
        float sv, cv; __sincosf(ang, &sv, &cv);
        float2 w1 = make_float2(cv, sv), w = w1;
        a[1] = cmul(a[1], w);
#pragma unroll
        for (int i = 2; i < 8; i++) { w = cmul(w, w1); a[i] = cmul(a[i], w); }
    }
    radix8<INV>(a);
#pragma unroll
    for (int i = 0; i < 8; i++) { int p = sidx(base + i * ST); re[p] = a[i].x; im[p] = a[i].y; }
}

// stage 3 leaving results in registers: a[k] = out[t + 512*k]
template <bool INV>
__device__ __forceinline__ void stage3_reg(const float* re, const float* im, int t, float2 a[8]) {
#pragma unroll
    for (int i = 0; i < 8; i++) { int p = sidx(t + i * 512); a[i] = make_float2(re[p], im[p]); }
    if (t) {
        float ang = (INV ? 6.283185307179586f : -6.283185307179586f) * (float)t / 4096.0f;
        float sv, cv; __sincosf(ang, &sv, &cv);
        float2 w1 = make_float2(cv, sv), w = w1;
        a[1] = cmul(a[1], w);
#pragma unroll
        for (int i = 2; i < 8; i++) { w = cmul(w, w1); a[i] = cmul(a[i], w); }
    }
    radix8<INV>(a);
}

template <bool INV>
__device__ __forceinline__ void fft_full(float* re, float* im, int t) {
    stage0<INV>(re, im, t); __syncthreads();
    stage<INV, 1>(re, im, t); __syncthreads();
    stage<INV, 2>(re, im, t); __syncthreads();
    stage<INV, 3>(re, im, t); __syncthreads();
}

// ---------------------------------------------------------------------------
// Kernel A: squash + rfft(8192) via packed 4096-pt FFT -> g_Kf (scaled 1/NC)
// ---------------------------------------------------------------------------
__global__ __launch_bounds__(512, 2) void build_kf_kernel(const float* __restrict__ kparam) {
    __shared__ float sre[SMSZ], sim[SMSZ];
    int t = threadIdx.x, h = blockIdx.x;
    const float2* kp2 = (const float2*)(kparam + (size_t)h * Ll);
    for (int m = t; m < 2048; m += 512) {
        float2 v = kp2[m];
        float s0 = fabsf(v.x) - LAMBDA; float a = (s0 > 0.f) ? copysignf(s0, v.x) : 0.f;
        float s1 = fabsf(v.y) - LAMBDA; float b = (s1 > 0.f) ? copysignf(s1, v.y) : 0.f;
        int p = sidx(m); sre[p] = a; sim[p] = b;
    }
    for (int m = 2048 + t; m < 4096; m += 512) { int p = sidx(m); sre[p] = 0.f; sim[p] = 0.f; }
    __syncthreads();

    fft_full<false>(sre, sim, t);

    float2* out = g_Kf + (size_t)h * (NC + 1);
    const float scale = 1.0f / (float)NC;
    for (int k = t; k <= NC / 2; k += 512) {
        if (k == 0) {
            float2 Z0 = make_float2(sre[sidx(0)], sim[sidx(0)]);
            out[0]  = make_float2((Z0.x + Z0.y) * scale, 0.f);
            out[NC] = make_float2((Z0.x - Z0.y) * scale, 0.f);
        } else if (k == NC / 2) {
            int p = sidx(NC / 2);
            out[NC / 2] = make_float2(sre[p] * scale, -sim[p] * scale);
        } else {
            int j = NC - k;
            int pk = sidx(k), pj = sidx(j);
            float2 Zk = make_float2(sre[pk], sim[pk]);
            float2 Zj = make_float2(sre[pj], sim[pj]);
            float2 E = make_float2(0.5f * (Zk.x + Zj.x),  0.5f * (Zk.y - Zj.y));
            float2 O = make_float2(0.5f * (Zk.y + Zj.y), -0.5f * (Zk.x - Zj.x));
            float sv, cv; __sincosf(-3.14159265358979f * (float)k / (float)NC, &sv, &cv);
            float2 W  = make_float2(cv, sv);
            float2 Wj = make_float2(-cv, sv);
            float2 Xk = cadd(E, cmul(W, O));
            float2 Xj = cadd(conjf2(E), cmul(Wj, conjf2(O)));
            out[k] = cscale(Xk, scale);
            out[j] = cscale(Xj, scale);
        }
    }
}

// ---------------------------------------------------------------------------
// Kernel B: rfft(u) -> *Kf -> irfft -> + D*u -> exact GELU, per (b,h) CTA
// ---------------------------------------------------------------------------
__global__ __launch_bounds__(512, 2) void conv_kernel(const float* __restrict__ u,
                                                      const float* __restrict__ D) {
    __shared__ float sre[SMSZ], sim[SMSZ];
    int t = threadIdx.x, h = blockIdx.x, b = blockIdx.y;
    const float2* u2 = (const float2*)(u + ((size_t)(b * Hh + h)) * Ll);

    for (int m = t; m < 2048; m += 512) { float2 v = u2[m]; int p = sidx(m); sre[p] = v.x; sim[p] = v.y; }
    for (int m = 2048 + t; m < 4096; m += 512) { int p = sidx(m); sre[p] = 0.f; sim[p] = 0.f; }
    __syncthreads();

    fft_full<false>(sre, sim, t);

    // pointwise: unpack packed-real spectrum, multiply by Kf, repack
    const float2* Kf = g_Kf + (size_t)h * (NC + 1);
    for (int k = t; k <= NC / 2; k += 512) {
        if (k == 0) {
            int p0 = sidx(0);
            float2 Z0 = make_float2(sre[p0], sim[p0]);
            float U0 = Z0.x + Z0.y, UN = Z0.x - Z0.y;
            float2 Y0 = cscale(Kf[0], U0);
            float2 YN = cscale(Kf[NC], UN);
            float2 Ey = make_float2(0.5f * (Y0.x + YN.x), 0.5f * (Y0.y - YN.y));
            float2 Oy = make_float2(0.5f * (Y0.x - YN.x), 0.5f * (Y0.y + YN.y));
            sre[p0] = Ey.x - Oy.y; sim[p0] = Ey.y + Oy.x;
        } else if (k == NC / 2) {
            int p = sidx(NC / 2);
            float2 Zm = make_float2(sre[p], sim[p]);
            float2 Y = cmul(conjf2(Zm), Kf[NC / 2]);
            sre[p] = Y.x; sim[p] = -Y.y;
        } else {
            int j = NC - k;
            int pk = sidx(k), pj = sidx(j);
            float2 Zk = make_float2(sre[pk], sim[pk]);
            float2 Zj = make_float2(sre[pj], sim[pj]);
            float2 E = make_float2(0.5f * (Zk.x + Zj.x),  0.5f * (Zk.y - Zj.y));
            float2 O = make_float2(0.5f * (Zk.y + Zj.y), -0.5f * (Zk.x - Zj.x));
            float sv, cv; __sincosf(-3.14159265358979f * (float)k / (float)NC, &sv, &cv);
            float2 W  = make_float2(cv, sv);
            float2 Wj = make_float2(-cv, sv);
            float2 Uk = cadd(E, cmul(W, O));
            float2 Uj = cadd(conjf2(E), cmul(Wj, conjf2(O)));
            float2 Yk = cmul(Uk, Kf[k]);
            float2 Yj = cmul(Uj, Kf[j]);
            float2 Ey = make_float2(0.5f * (Yk.x + Yj.x), 0.5f * (Yk.y - Yj.y));
            float2 T  = make_float2(0.5f * (Yk.x - Yj.x), 0.5f * (Yk.y + Yj.y));
            float2 Oy  = cmul(conjf2(W), T);
            float2 OyJ = cmul(W, conjf2(T));
            sre[pk] = Ey.x - Oy.y;   sim[pk] = Ey.y + Oy.x;
            sre[pj] = Ey.x - OyJ.y;  sim[pj] = -Ey.y + OyJ.x;
        }
    }
    __syncthreads();

    // inverse FFT; final stage in registers, fused epilogue
    stage0<true>(sre, sim, t); __syncthreads();
    stage<true, 1>(sre, sim, t); __syncthreads();
    stage<true, 2>(sre, sim, t); __syncthreads();
    float2 a[8];
    stage3_reg<true>(sre, sim, t, a);

    float dcoef = D[h];
    float2* yo = (float2*)(g_Yact + ((size_t)(b * Hh + h)) * Ll);
    const float INV_SQRT2 = 0.70710678118654752f;
#pragma unroll
    for (int i = 0; i < 4; i++) {          // outputs n = t + 512*i < 2048 only
        int n = t + 512 * i;
        float2 uv = u2[n];
        float y0 = a[i].x + dcoef * uv.x;
        float y1 = a[i].y + dcoef * uv.y;
        y0 = 0.5f * y0 * (1.0f + erff(y0 * INV_SQRT2));
        y1 = 0.5f * y1 * (1.0f + erff(y1 * INV_SQRT2));
        yo[n] = make_float2(y0, y1);
    }
}

// ---------------------------------------------------------------------------
// Kernel C: out = silu(W @ Yact + b) with packed f32x2 FMA (2x FFMA rate)
// 128x128x16 tile, 256 threads, 8x8 microtile.
// ---------------------------------------------------------------------------
typedef unsigned long long ull;

__device__ __forceinline__ ull pk2(float x, float y) {
    ull r; asm("mov.b64 %0, {%1,%2};" : "=l"(r) : "f"(x), "f"(y)); return r;
}
__device__ __forceinline__ ull fma2(ull a, ull b, ull c) {
    ull d; asm("fma.rn.f32x2 %0, %1, %2, %3;" : "=l"(d) : "l"(a), "l"(b), "l"(c)); return d;
}
__device__ __forceinline__ float2 upk(ull v) {
    float lo, hi; asm("mov.b64 {%0,%1}, %2;" : "=f"(lo), "=f"(hi) : "l"(v)); return make_float2(lo, hi);
}
__device__ __forceinline__ float silu_f(float x) { return x / (1.0f + __expf(-x)); }

#define GBK 16

__global__ __launch_bounds__(256, 2) void gemm_silu_kernel(const float* __restrict__ W,
                                                           const float* __restrict__ bias,
                                                           float* __restrict__ out) {
    __shared__ ull As2[GBK][128];   // W duplicated into pairs (w,w)  16KB
    __shared__ ull Bs2[GBK][64];    // Yact packed column pairs       8KB
    int tid = threadIdx.x;
    int l0 = blockIdx.x * 128;
    int v0 = blockIdx.y * 128;
    int b  = blockIdx.z;
    const float* Y = g_Yact + (size_t)b * Hh * Ll;

    ull acc[8][4];
#pragma unroll
    for (int i = 0; i < 8; i++)
#pragma unroll
        for (int p = 0; p < 4; p++) acc[i][p] = 0ULL;

    int tm = tid >> 4, tn = tid & 15;
    int wrow = tid >> 1, wc8 = (tid & 1) * 8;
    int yr = tid >> 4, yc8 = (tid & 15) * 8;

    for (int k0 = 0; k0 < Hh; k0 += GBK) {
        const float* wp = W + (size_t)(v0 + wrow) * Hh + k0 + wc8;
        float4 w0 = *(const float4*)(wp);
        float4 w1 = *(const float4*)(wp + 4);
        As2[wc8 + 0][wrow] = pk2(w0.x, w0.x);
        As2[wc8 + 1][wrow] = pk2(w0.y, w0.y);
        As2[wc8 + 2][wrow] = pk2(w0.z, w0.z);
        As2[wc8 + 3][wrow] = pk2(w0.w, w0.w);
        As2[wc8 + 4][wrow] = pk2(w1.x, w1.x);
        As2[wc8 + 5][wrow] = pk2(w1.y, w1.y);
        As2[wc8 + 6][wrow] = pk2(w1.z, w1.z);
        As2[wc8 + 7][wrow] = pk2(w1.w, w1.w);

        const float* yp = Y + (size_t)(k0 + yr) * Ll + l0 + yc8;
        float4 y0 = *(const float4*)(yp);
        float4 y1 = *(const float4*)(yp + 4);
        int bc = yc8 >> 1;
        Bs2[yr][bc + 0] = pk2(y0.x, y0.y);
        Bs2[yr][bc + 1] = pk2(y0.z, y0.w);
        Bs2[yr][bc + 2] = pk2(y1.x, y1.y);
        Bs2[yr][bc + 3] = pk2(y1.z, y1.w);
        __syncthreads();

#pragma unroll
        for (int kk = 0; kk < GBK; kk++) {
            ull aa[8], bb[4];
            ulonglong2 av;
#pragma unroll
            for (int q = 0; q < 4; q++) {
                av = *(const ulonglong2*)&As2[kk][tm * 8 + 2 * q];
                aa[2 * q] = av.x; aa[2 * q + 1] = av.y;
            }
#pragma unroll
            for (int q = 0; q < 2; q++) {
                ulonglong2 bv = *(const ulonglong2*)&Bs2[kk][tn * 4 + 2 * q];
                bb[2 * q] = bv.x; bb[2 * q + 1] = bv.y;
            }
#pragma unroll
            for (int i = 0; i < 8; i++)
#pragma unroll
                for (int p = 0; p < 4; p++)
                    acc[i][p] = fma2(aa[i], bb[p], acc[i][p]);
        }
        __syncthreads();
    }

#pragma unroll
    for (int i = 0; i < 8; i++) {
        int v = v0 + tm * 8 + i;
        float bv = bias[v];
        float o[8];
#pragma unroll
        for (int p = 0; p < 4; p++) {
            float2 xy = upk(acc[i][p]);
            o[2 * p]     = silu_f(xy.x + bv);
            o[2 * p + 1] = silu_f(xy.y + bv);
        }
        float4* dst = (float4*)(out + ((size_t)(b * Hh + v)) * Ll + l0 + tn * 8);
        dst[0] = make_float4(o[0], o[1], o[2], o[3]);
        dst[1] = make_float4(o[4], o[5], o[6], o[7]);
    }
}

extern "C" void kernel_launch(void* const* d_in, const int* in_sizes, int n_in,
                              void* d_out, int out_size) {
    const float* u    = (const float*)d_in[0];   // (16, 512, 4096)
    const float* kern = (const float*)d_in[1];   // (1, 512, 4096)
    const float* D    = (const float*)d_in[2];   // (1, 512)
    const float* Wout = (const float*)d_in[3];   // (512, 512)
    const float* bout = (const float*)d_in[4];   // (512,)
    float* out = (float*)d_out;                  // (16, 512, 4096)

    build_kf_kernel<<<Hh, 512>>>(kern);
    conv_kernel<<<dim3(Hh, Bb), 512>>>(u, D);
    gemm_silu_kernel<<<dim3(Ll / 128, Hh / 128, Bb), 256>>>(Wout, bout, out);
}

// round 4
// speedup vs baseline: 3.0132x; 1.7416x over previous
#include <cuda_runtime.h>
#include <cuda_bf16.h>
#include <math.h>
#include <stdint.h>

#define Bb 16
#define Hh 512
#define Ll 4096
#define NC 4096
#define LAMBDA 0.001f

// Scratch (no runtime allocation allowed)
__device__ float2   g_Kf[Hh * (NC + 1)];                    // kernel spectrum, 1/NC folded in
__device__ uint32_t g_Yhi[(size_t)Bb * Hh * Ll / 2];        // bf16x2 hi of gelu(conv+skip)
__device__ uint32_t g_Ylo[(size_t)Bb * Hh * Ll / 2];        // bf16x2 lo residual

__device__ __forceinline__ float2 cadd(float2 a, float2 b) { return make_float2(a.x + b.x, a.y + b.y); }
__device__ __forceinline__ float2 csub(float2 a, float2 b) { return make_float2(a.x - b.x, a.y - b.y); }
__device__ __forceinline__ float2 cmul(float2 a, float2 b) {
    return make_float2(a.x * b.x - a.y * b.y, a.x * b.y + a.y * b.x);
}
__device__ __forceinline__ float2 conjf2(float2 a) { return make_float2(a.x, -a.y); }
__device__ __forceinline__ float2 cscale(float2 a, float s) { return make_float2(a.x * s, a.y * s); }

__device__ __forceinline__ int sidx(int n) { return n + (n >> 4); }
#define SMSZ (4096 + 256)

// ---------------------------------------------------------------------------
// radix-8 FFT machinery (validated in round 2)
// ---------------------------------------------------------------------------
template <bool INV>
__device__ __forceinline__ void radix8(float2 a[8]) {
    const float C = 0.70710678118654752440f;
    float2 t0 = cadd(a[0], a[4]);
    float2 t1 = csub(a[0], a[4]);
    float2 t2 = cadd(a[2], a[6]);
    float2 t3;
    { float2 d = csub(a[2], a[6]); t3 = INV ? make_float2(-d.y, d.x) : make_float2(d.y, -d.x); }
    float2 E0 = cadd(t0, t2), E2 = csub(t0, t2);
    float2 E1 = cadd(t1, t3), E3 = csub(t1, t3);
    float2 s0 = cadd(a[1], a[5]);
    float2 s1 = csub(a[1], a[5]);
    float2 s2 = cadd(a[3], a[7]);
    float2 s3;
    { float2 d = csub(a[3], a[7]); s3 = INV ? make_float2(-d.y, d.x) : make_float2(d.y, -d.x); }
    float2 O0 = cadd(s0, s2), O2 = csub(s0, s2);
    float2 O1 = cadd(s1, s3), O3 = csub(s1, s3);
    float2 O1w, O2w, O3w;
    if (!INV) {
        O1w = make_float2(C * (O1.x + O1.y), C * (O1.y - O1.x));
        O2w = make_float2(O2.y, -O2.x);
        O3w = make_float2(C * (O3.y - O3.x), -C * (O3.x + O3.y));
    } else {
        O1w = make_float2(C * (O1.x - O1.y), C * (O1.y + O1.x));
        O2w = make_float2(-O2.y, O2.x);
        O3w = make_float2(-C * (O3.x + O3.y), C * (O3.x - O3.y));
    }
    a[0] = cadd(E0, O0);  a[4] = csub(E0, O0);
    a[1] = cadd(E1, O1w); a[5] = csub(E1, O1w);
    a[2] = cadd(E2, O2w); a[6] = csub(E2, O2w);
    a[3] = cadd(E3, O3w); a[7] = csub(E3, O3w);
}

template <bool INV>
__device__ __forceinline__ void stage0(float* re, float* im, int t) {
    int r3 = ((t & 7) << 6) | (t & 56) | (t >> 6);
    float2 a[8];
#pragma unroll
    for (int i = 0; i < 8; i++) { int p = sidx(i * 512 + r3); a[i] = make_float2(re[p], im[p]); }
    __syncthreads();
    radix8<INV>(a);
#pragma unroll
    for (int i = 0; i < 8; i++) { int p = sidx(8 * t + i); re[p] = a[i].x; im[p] = a[i].y; }
}

template <bool INV, int S>
__device__ __forceinline__ void stage(float* re, float* im, int t) {
    constexpr int ST = 1 << (3 * S);
    constexpr int M8 = ST * 8;
    int j = t & (ST - 1);
    int base = ((t >> (3 * S)) << (3 * (S + 1))) + j;
    float2 a[8];
#pragma unroll
    for (int i = 0; i < 8; i++) { int p = sidx(base + i * ST); a[i] = make_float2(re[p], im[p]); }
    if (j) {
        float ang = (INV ? 6.283185307179586f : -6.283185307179586f) * (float)j / (float)M8;
        float sv, cv; __sincosf(ang, &sv, &cv);
        float2 w1 = make_float2(cv, sv), w = w1;
        a[1] = cmul(a[1], w);
#pragma unroll
        for (int i = 2; i < 8; i++) { w = cmul(w, w1); a[i] = cmul(a[i], w); }
    }
    radix8<INV>(a);
#pragma unroll
    for (int i = 0; i < 8; i++) { int p = sidx(base + i * ST); re[p] = a[i].x; im[p] = a[i].y; }
}

template <bool INV>
__device__ __forceinline__ void stage3_reg(const float* re, const float* im, int t, float2 a[8]) {
#pragma unroll
    for (int i = 0; i < 8; i++) { int p = sidx(t + i * 512); a[i] = make_float2(re[p], im[p]); }
    if (t) {
        float ang = (INV ? 6.283185307179586f : -6.283185307179586f) * (float)t / 4096.0f;
        float sv, cv; __sincosf(ang, &sv, &cv);
        float2 w1 = make_float2(cv, sv), w = w1;
        a[1] = cmul(a[1], w);
#pragma unroll
        for (int i = 2; i < 8; i++) { w = cmul(w, w1); a[i] = cmul(a[i], w); }
    }
    radix8<INV>(a);
}

template <bool INV>
__device__ __forceinline__ void fft_full(float* re, float* im, int t) {
    stage0<INV>(re, im, t); __syncthreads();
    stage<INV, 1>(re, im, t); __syncthreads();
    stage<INV, 2>(re, im, t); __syncthreads();
    stage<INV, 3>(re, im, t); __syncthreads();
}

// ---------------------------------------------------------------------------
// Kernel A: squash + rfft(8192) -> g_Kf (scaled 1/NC)
// ---------------------------------------------------------------------------
__global__ __launch_bounds__(512, 2) void build_kf_kernel(const float* __restrict__ kparam) {
    __shared__ float sre[SMSZ], sim[SMSZ];
    int t = threadIdx.x, h = blockIdx.x;
    const float2* kp2 = (const float2*)(kparam + (size_t)h * Ll);
    for (int m = t; m < 2048; m += 512) {
        float2 v = kp2[m];
        float s0 = fabsf(v.x) - LAMBDA; float a = (s0 > 0.f) ? copysignf(s0, v.x) : 0.f;
        float s1 = fabsf(v.y) - LAMBDA; float b = (s1 > 0.f) ? copysignf(s1, v.y) : 0.f;
        int p = sidx(m); sre[p] = a; sim[p] = b;
    }
    for (int m = 2048 + t; m < 4096; m += 512) { int p = sidx(m); sre[p] = 0.f; sim[p] = 0.f; }
    __syncthreads();

    fft_full<false>(sre, sim, t);

    float2* out = g_Kf + (size_t)h * (NC + 1);
    const float scale = 1.0f / (float)NC;
    for (int k = t; k <= NC / 2; k += 512) {
        if (k == 0) {
            float2 Z0 = make_float2(sre[sidx(0)], sim[sidx(0)]);
            out[0]  = make_float2((Z0.x + Z0.y) * scale, 0.f);
            out[NC] = make_float2((Z0.x - Z0.y) * scale, 0.f);
        } else if (k == NC / 2) {
            int p = sidx(NC / 2);
            out[NC / 2] = make_float2(sre[p] * scale, -sim[p] * scale);
        } else {
            int j = NC - k;
            int pk = sidx(k), pj = sidx(j);
            float2 Zk = make_float2(sre[pk], sim[pk]);
            float2 Zj = make_float2(sre[pj], sim[pj]);
            float2 E = make_float2(0.5f * (Zk.x + Zj.x),  0.5f * (Zk.y - Zj.y));
            float2 O = make_float2(0.5f * (Zk.y + Zj.y), -0.5f * (Zk.x - Zj.x));
            float sv, cv; __sincosf(-3.14159265358979f * (float)k / (float)NC, &sv, &cv);
            float2 W  = make_float2(cv, sv);
            float2 Wj = make_float2(-cv, sv);
            float2 Xk = cadd(E, cmul(W, O));
            float2 Xj = cadd(conjf2(E), cmul(Wj, conjf2(O)));
            out[k] = cscale(Xk, scale);
            out[j] = cscale(Xj, scale);
        }
    }
}

// ---------------------------------------------------------------------------
// Kernel B: rfft(u) -> *Kf -> irfft -> + D*u -> exact GELU -> bf16 hi/lo
// ---------------------------------------------------------------------------
__global__ __launch_bounds__(512, 2) void conv_kernel(const float* __restrict__ u,
                                                      const float* __restrict__ D) {
    __shared__ float sre[SMSZ], sim[SMSZ];
    int t = threadIdx.x, h = blockIdx.x, b = blockIdx.y;
    const float2* u2 = (const float2*)(u + ((size_t)(b * Hh + h)) * Ll);

    for (int m = t; m < 2048; m += 512) { float2 v = u2[m]; int p = sidx(m); sre[p] = v.x; sim[p] = v.y; }
    for (int m = 2048 + t; m < 4096; m += 512) { int p = sidx(m); sre[p] = 0.f; sim[p] = 0.f; }
    __syncthreads();

    fft_full<false>(sre, sim, t);

    const float2* Kf = g_Kf + (size_t)h * (NC + 1);
    for (int k = t; k <= NC / 2; k += 512) {
        if (k == 0) {
            int p0 = sidx(0);
            float2 Z0 = make_float2(sre[p0], sim[p0]);
            float U0 = Z0.x + Z0.y, UN = Z0.x - Z0.y;
            float2 Y0 = cscale(Kf[0], U0);
            float2 YN = cscale(Kf[NC], UN);
            float2 Ey = make_float2(0.5f * (Y0.x + YN.x), 0.5f * (Y0.y - YN.y));
            float2 Oy = make_float2(0.5f * (Y0.x - YN.x), 0.5f * (Y0.y + YN.y));
            sre[p0] = Ey.x - Oy.y; sim[p0] = Ey.y + Oy.x;
        } else if (k == NC / 2) {
            int p = sidx(NC / 2);
            float2 Zm = make_float2(sre[p], sim[p]);
            float2 Y = cmul(conjf2(Zm), Kf[NC / 2]);
            sre[p] = Y.x; sim[p] = -Y.y;
        } else {
            int j = NC - k;
            int pk = sidx(k), pj = sidx(j);
            float2 Zk = make_float2(sre[pk], sim[pk]);
            float2 Zj = make_float2(sre[pj], sim[pj]);
            float2 E = make_float2(0.5f * (Zk.x + Zj.x),  0.5f * (Zk.y - Zj.y));
            float2 O = make_float2(0.5f * (Zk.y + Zj.y), -0.5f * (Zk.x - Zj.x));
            float sv, cv; __sincosf(-3.14159265358979f * (float)k / (float)NC, &sv, &cv);
            float2 W  = make_float2(cv, sv);
            float2 Wj = make_float2(-cv, sv);
            float2 Uk = cadd(E, cmul(W, O));
            float2 Uj = cadd(conjf2(E), cmul(Wj, conjf2(O)));
            float2 Yk = cmul(Uk, Kf[k]);
            float2 Yj = cmul(Uj, Kf[j]);
            float2 Ey = make_float2(0.5f * (Yk.x + Yj.x), 0.5f * (Yk.y - Yj.y));
            float2 T  = make_float2(0.5f * (Yk.x - Yj.x), 0.5f * (Yk.y + Yj.y));
            float2 Oy  = cmul(conjf2(W), T);
            float2 OyJ = cmul(W, conjf2(T));
            sre[pk] = Ey.x - Oy.y;   sim[pk] = Ey.y + Oy.x;
            sre[pj] = Ey.x - OyJ.y;  sim[pj] = -Ey.y + OyJ.x;
        }
    }
    __syncthreads();

    stage0<true>(sre, sim, t); __syncthreads();
    stage<true, 1>(sre, sim, t); __syncthreads();
    stage<true, 2>(sre, sim, t); __syncthreads();
    float2 a[8];
    stage3_reg<true>(sre, sim, t, a);

    float dcoef = D[h];
    uint32_t* yh = g_Yhi + ((size_t)(b * Hh + h)) * (Ll / 2);
    uint32_t* yl = g_Ylo + ((size_t)(b * Hh + h)) * (Ll / 2);
    const float INV_SQRT2 = 0.70710678118654752f;
#pragma unroll
    for (int i = 0; i < 4; i++) {
        int n = t + 512 * i;
        float2 uv = u2[n];
        float y0 = a[i].x + dcoef * uv.x;
        float y1 = a[i].y + dcoef * uv.y;
        y0 = 0.5f * y0 * (1.0f + erff(y0 * INV_SQRT2));
        y1 = 0.5f * y1 * (1.0f + erff(y1 * INV_SQRT2));
        __nv_bfloat16 h0 = __float2bfloat16(y0);
        __nv_bfloat16 h1 = __float2bfloat16(y1);
        float r0 = y0 - __bfloat162float(h0);
        float r1 = y1 - __bfloat162float(h1);
        __nv_bfloat16 l0b = __float2bfloat16(r0);
        __nv_bfloat16 l1b = __float2bfloat16(r1);
        yh[n] = (uint32_t)__bfloat16_as_ushort(h0) | ((uint32_t)__bfloat16_as_ushort(h1) << 16);
        yl[n] = (uint32_t)__bfloat16_as_ushort(l0b) | ((uint32_t)__bfloat16_as_ushort(l1b) << 16);
    }
}

// ---------------------------------------------------------------------------
// Kernel C: warp-MMA (HMMA) bf16 GEMM, 3-term precision split, bias + SiLU.
// CTA 128(v) x 128(l), K chunks of 64. 8 warps, warp tile 64x32.
// A smem: [128 rows][64 k] bf16, row stride 144B (conflict-free ldmatrix).
// B smem: [64 k][128 l] bf16, 256B rows, XOR-swizzled 16B blocks.
// ---------------------------------------------------------------------------
#define AK 64
#define ASTRIDE 144
#define OFF_AHI 0
#define OFF_ALO (128 * ASTRIDE)
#define OFF_BHI (2 * 128 * ASTRIDE)
#define OFF_BLO (OFF_BHI + 64 * 256)
#define GEMM_SMEM (OFF_BLO + 64 * 256)   // 69632 bytes

__device__ __forceinline__ uint32_t smem_u32(const void* p) {
    uint32_t a;
    asm("{ .reg .u64 t; cvta.to.shared.u64 t, %1; cvt.u32.u64 %0, t; }" : "=r"(a) : "l"(p));
    return a;
}
__device__ __forceinline__ void ldsm4(uint32_t r[4], uint32_t addr) {
    asm volatile("ldmatrix.sync.aligned.m8n8.x4.shared.b16 {%0,%1,%2,%3}, [%4];"
                 : "=r"(r[0]), "=r"(r[1]), "=r"(r[2]), "=r"(r[3]) : "r"(addr));
}
__device__ __forceinline__ void ldsm4t(uint32_t r[4], uint32_t addr) {
    asm volatile("ldmatrix.sync.aligned.m8n8.x4.trans.shared.b16 {%0,%1,%2,%3}, [%4];"
                 : "=r"(r[0]), "=r"(r[1]), "=r"(r[2]), "=r"(r[3]) : "r"(addr));
}
__device__ __forceinline__ void mma16816(float c[4], const uint32_t a[4], const uint32_t b[2]) {
    asm volatile(
        "mma.sync.aligned.m16n8k16.row.col.f32.bf16.bf16.f32 "
        "{%0,%1,%2,%3}, {%4,%5,%6,%7}, {%8,%9}, {%0,%1,%2,%3};"
        : "+f"(c[0]), "+f"(c[1]), "+f"(c[2]), "+f"(c[3])
        : "r"(a[0]), "r"(a[1]), "r"(a[2]), "r"(a[3]), "r"(b[0]), "r"(b[1]));
}
__device__ __forceinline__ float silu_f(float x) { return x / (1.0f + __expf(-x)); }
// B smem 16B-block swizzle: block cb (0..15) in k-row k
__device__ __forceinline__ int bswz(int k, int cb) { return (cb & 8) | ((cb ^ k) & 7); }

__global__ __launch_bounds__(256, 2) void gemm_silu_kernel(const float* __restrict__ W,
                                                           const float* __restrict__ bias,
                                                           float* __restrict__ out) {
    extern __shared__ char smem[];
    uint32_t sb = smem_u32(smem);
    int tid = threadIdx.x;
    int wid = tid >> 5;
    int lane = tid & 31;

    int v0 = blockIdx.x * 128;           // vt fastest -> 4 CTAs share B tile in L2
    int l0 = blockIdx.y * 128;
    int b  = blockIdx.z;

    int wm = wid & 1;                    // 2 warp rows of 64
    int wn = wid >> 1;                   // 4 warp cols of 32

    const __nv_bfloat16* Yh = (const __nv_bfloat16*)g_Yhi;
    const __nv_bfloat16* Yl = (const __nv_bfloat16*)g_Ylo;

    float acc[4][4][4];
#pragma unroll
    for (int i = 0; i < 4; i++)
#pragma unroll
        for (int j = 0; j < 4; j++)
#pragma unroll
            for (int q = 0; q < 4; q++) acc[i][j][q] = 0.f;

    // A/B smem addresses for ldmatrix (per thread)
    // A: row = mbase + lane%16, 16B col block = lane/16 within 32B kstep group
    // B: k-row = lane%16 (+kstep*16), col block = jbase/8 + lane/16
    for (int c = 0; c < 8; c++) {
        int k0 = c * AK;

        // ---- load A tile: W[v0+r][k0..k0+63] -> bf16 hi/lo
        {
            int r = tid >> 1;
            int half = tid & 1;            // 32 floats each
            const float* wp = W + (size_t)(v0 + r) * Hh + k0 + half * 32;
            char* ah = smem + OFF_AHI + r * ASTRIDE + half * 64;
            char* al = smem + OFF_ALO + r * ASTRIDE + half * 64;
#pragma unroll
            for (int i = 0; i < 8; i++) {
                float4 w4 = *(const float4*)(wp + 4 * i);
                __nv_bfloat16 h0 = __float2bfloat16(w4.x);
                __nv_bfloat16 h1 = __float2bfloat16(w4.y);
                __nv_bfloat16 h2 = __float2bfloat16(w4.z);
                __nv_bfloat16 h3 = __float2bfloat16(w4.w);
                __nv_bfloat16 q0 = __float2bfloat16(w4.x - __bfloat162float(h0));
                __nv_bfloat16 q1 = __float2bfloat16(w4.y - __bfloat162float(h1));
                __nv_bfloat16 q2 = __float2bfloat16(w4.z - __bfloat162float(h2));
                __nv_bfloat16 q3 = __float2bfloat16(w4.w - __bfloat162float(h3));
                uint2 hp, lp;
                hp.x = (uint32_t)__bfloat16_as_ushort(h0) | ((uint32_t)__bfloat16_as_ushort(h1) << 16);
                hp.y = (uint32_t)__bfloat16_as_ushort(h2) | ((uint32_t)__bfloat16_as_ushort(h3) << 16);
                lp.x = (uint32_t)__bfloat16_as_ushort(q0) | ((uint32_t)__bfloat16_as_ushort(q1) << 16);
                lp.y = (uint32_t)__bfloat16_as_ushort(q2) | ((uint32_t)__bfloat16_as_ushort(q3) << 16);
                *(uint2*)(ah + 8 * i) = hp;
                *(uint2*)(al + 8 * i) = lp;
            }
        }

        // ---- load B tile: Y[k0+k][l0..l0+127] (16B chunks, swizzled store)
        {
            int cb = tid & 15;
#pragma unroll
            for (int i = 0; i < 4; i++) {
                int k = (tid >> 4) + 16 * i;
                size_t ge = ((size_t)(b * Hh) + k0 + k) * Ll + l0 + cb * 8;
                uint4 vh = *(const uint4*)(Yh + ge);
                uint4 vl = *(const uint4*)(Yl + ge);
                int so = k * 256 + bswz(k, cb) * 16;
                *(uint4*)(smem + OFF_BHI + so) = vh;
                *(uint4*)(smem + OFF_BLO + so) = vl;
            }
        }
        __syncthreads();

#pragma unroll
        for (int ks = 0; ks < 4; ks++) {
            // B fragments: two x4.trans per term cover n = wn*32 .. +31
            uint32_t bh[2][4], bl[2][4];
#pragma unroll
            for (int g = 0; g < 2; g++) {
                int krow = ks * 16 + (lane & 15);
                int cb = (wn * 32 + g * 16) / 8 + (lane >> 4);
                uint32_t baddr = sb + OFF_BHI + krow * 256 + bswz(krow, cb) * 16;
                ldsm4t(bh[g], baddr);
                ldsm4t(bl[g], baddr + (OFF_BLO - OFF_BHI));
            }
#pragma unroll
            for (int mt = 0; mt < 4; mt++) {
                int arow = wm * 64 + mt * 16 + (lane & 15);
                uint32_t aaddr = sb + OFF_AHI + arow * ASTRIDE + ks * 32 + (lane >> 4) * 16;
                uint32_t ahf[4], alf[4];
                ldsm4(ahf, aaddr);
                ldsm4(alf, aaddr + (uint32_t)(OFF_ALO - OFF_AHI));
#pragma unroll
                for (int nt = 0; nt < 4; nt++) {
                    const uint32_t* bhx = &bh[nt >> 1][(nt & 1) * 2];
                    const uint32_t* blx = &bl[nt >> 1][(nt & 1) * 2];
                    mma16816(acc[mt][nt], ahf, bhx);
                    mma16816(acc[mt][nt], ahf, blx);
                    mma16816(acc[mt][nt], alf, bhx);
                }
            }
        }
        __syncthreads();
    }

    // ---- epilogue: bias + SiLU, float2 stores
    int g = lane >> 2;           // 0..7
    int cq = (lane & 3) * 2;     // col pair
#pragma unroll
    for (int mt = 0; mt < 4; mt++) {
        int vbase = v0 + wm * 64 + mt * 16 + g;
        float bv0 = bias[vbase];
        float bv1 = bias[vbase + 8];
        float* row0 = out + ((size_t)(b * Hh) + vbase) * Ll;
        float* row1 = row0 + 8 * Ll;
#pragma unroll
        for (int nt = 0; nt < 4; nt++) {
            int lc = l0 + wn * 32 + nt * 8 + cq;
            float2 o0, o1;
            o0.x = silu_f(acc[mt][nt][0] + bv0);
            o0.y = silu_f(acc[mt][nt][1] + bv0);
            o1.x = silu_f(acc[mt][nt][2] + bv1);
            o1.y = silu_f(acc[mt][nt][3] + bv1);
            *(float2*)(row0 + lc) = o0;
            *(float2*)(row1 + lc) = o1;
        }
    }
}

extern "C" void kernel_launch(void* const* d_in, const int* in_sizes, int n_in,
                              void* d_out, int out_size) {
    const float* u    = (const float*)d_in[0];   // (16, 512, 4096)
    const float* kern = (const float*)d_in[1];   // (1, 512, 4096)
    const float* D    = (const float*)d_in[2];   // (1, 512)
    const float* Wout = (const float*)d_in[3];   // (512, 512)
    const float* bout = (const float*)d_in[4];   // (512,)
    float* out = (float*)d_out;                  // (16, 512, 4096)

    cudaFuncSetAttribute(gemm_silu_kernel, cudaFuncAttributeMaxDynamicSharedMemorySize, GEMM_SMEM);

    build_kf_kernel<<<Hh, 512>>>(kern);
    conv_kernel<<<dim3(Hh, Bb), 512>>>(u, D);
    gemm_silu_kernel<<<dim3(4, 32, 16), 256, GEMM_SMEM>>>(Wout, bout, out);
}

// round 5
// speedup vs baseline: 3.1306x; 1.0390x over previous
#include <cuda_runtime.h>
#include <cuda_bf16.h>
#include <math.h>
#include <stdint.h>

#define Bb 16
#define Hh 512
#define Ll 4096
#define NC 4096
#define LAMBDA 0.001f

// Scratch (no runtime allocation allowed)
__device__ float4   g_Tab[(size_t)Hh * 4098];               // pointwise table: per (h,k) A,B / A',B'
__device__ uint32_t g_Yhi[(size_t)Bb * Hh * Ll / 2];        // bf16x2 hi of gelu(conv+skip)
__device__ uint32_t g_Ylo[(size_t)Bb * Hh * Ll / 2];        // bf16x2 lo residual
__device__ uint32_t g_Whi[Hh * Hh / 2];                     // W as bf16x2 hi, row-major [v][k]
__device__ uint32_t g_Wlo[Hh * Hh / 2];                     // W bf16x2 lo residual

__device__ __forceinline__ float2 cadd(float2 a, float2 b) { return make_float2(a.x + b.x, a.y + b.y); }
__device__ __forceinline__ float2 csub(float2 a, float2 b) { return make_float2(a.x - b.x, a.y - b.y); }
__device__ __forceinline__ float2 cmul(float2 a, float2 b) {
    return make_float2(a.x * b.x - a.y * b.y, a.x * b.y + a.y * b.x);
}
__device__ __forceinline__ float2 conjf2(float2 a) { return make_float2(a.x, -a.y); }
__device__ __forceinline__ float2 cscale(float2 a, float s) { return make_float2(a.x * s, a.y * s); }

__device__ __forceinline__ int sidx(int n) { return n + (n >> 4); }
#define SMSZ (4096 + 256)

// ---------------------------------------------------------------------------
// radix-8 FFT machinery (validated)
// ---------------------------------------------------------------------------
template <bool INV>
__device__ __forceinline__ void radix8(float2 a[8]) {
    const float C = 0.70710678118654752440f;
    float2 t0 = cadd(a[0], a[4]);
    float2 t1 = csub(a[0], a[4]);
    float2 t2 = cadd(a[2], a[6]);
    float2 t3;
    { float2 d = csub(a[2], a[6]); t3 = INV ? make_float2(-d.y, d.x) : make_float2(d.y, -d.x); }
    float2 E0 = cadd(t0, t2), E2 = csub(t0, t2);
    float2 E1 = cadd(t1, t3), E3 = csub(t1, t3);
    float2 s0 = cadd(a[1], a[5]);
    float2 s1 = csub(a[1], a[5]);
    float2 s2 = cadd(a[3], a[7]);
    float2 s3;
    { float2 d = csub(a[3], a[7]); s3 = INV ? make_float2(-d.y, d.x) : make_float2(d.y, -d.x); }
    float2 O0 = cadd(s0, s2), O2 = csub(s0, s2);
    float2 O1 = cadd(s1, s3), O3 = csub(s1, s3);
    float2 O1w, O2w, O3w;
    if (!INV) {
        O1w = make_float2(C * (O1.x + O1.y), C * (O1.y - O1.x));
        O2w = make_float2(O2.y, -O2.x);
        O3w = make_float2(C * (O3.y - O3.x), -C * (O3.x + O3.y));
    } else {
        O1w = make_float2(C * (O1.x - O1.y), C * (O1.y + O1.x));
        O2w = make_float2(-O2.y, O2.x);
        O3w = make_float2(-C * (O3.x + O3.y), C * (O3.x - O3.y));
    }
    a[0] = cadd(E0, O0);  a[4] = csub(E0, O0);
    a[1] = cadd(E1, O1w); a[5] = csub(E1, O1w);
    a[2] = cadd(E2, O2w); a[6] = csub(E2, O2w);
    a[3] = cadd(E3, O3w); a[7] = csub(E3, O3w);
}

template <bool INV>
__device__ __forceinline__ void stage0(float* re, float* im, int t) {
    int r3 = ((t & 7) << 6) | (t & 56) | (t >> 6);
    float2 a[8];
#pragma unroll
    for (int i = 0; i < 8; i++) { int p = sidx(i * 512 + r3); a[i] = make_float2(re[p], im[p]); }
    __syncthreads();
    radix8<INV>(a);
#pragma unroll
    for (int i = 0; i < 8; i++) { int p = sidx(8 * t + i); re[p] = a[i].x; im[p] = a[i].y; }
}

template <bool INV, int S>
__device__ __forceinline__ void stage(float* re, float* im, int t) {
    constexpr int ST = 1 << (3 * S);
    constexpr int M8 = ST * 8;
    int j = t & (ST - 1);
    int base = ((t >> (3 * S)) << (3 * (S + 1))) + j;
    float2 a[8];
#pragma unroll
    for (int i = 0; i < 8; i++) { int p = sidx(base + i * ST); a[i] = make_float2(re[p], im[p]); }
    if (j) {
        float ang = (INV ? 6.283185307179586f : -6.283185307179586f) * (float)j / (float)M8;
        float sv, cv; __sincosf(ang, &sv, &cv);
        float2 w1 = make_float2(cv, sv), w = w1;
        a[1] = cmul(a[1], w);
#pragma unroll
        for (int i = 2; i < 8; i++) { w = cmul(w, w1); a[i] = cmul(a[i], w); }
    }
    radix8<INV>(a);
#pragma unroll
    for (int i = 0; i < 8; i++) { int p = sidx(base + i * ST); re[p] = a[i].x; im[p] = a[i].y; }
}

template <bool INV>
__device__ __forceinline__ void stage3_reg(const float* re, const float* im, int t, float2 a[8]) {
#pragma unroll
    for (int i = 0; i < 8; i++) { int p = sidx(t + i * 512); a[i] = make_float2(re[p], im[p]); }
    if (t) {
        float ang = (INV ? 6.283185307179586f : -6.283185307179586f) * (float)t / 4096.0f;
        float sv, cv; __sincosf(ang, &sv, &cv);
        float2 w1 = make_float2(cv, sv), w = w1;
        a[1] = cmul(a[1], w);
#pragma unroll
        for (int i = 2; i < 8; i++) { w = cmul(w, w1); a[i] = cmul(a[i], w); }
    }
    radix8<INV>(a);
}

template <bool INV>
__device__ __forceinline__ void fft_full(float* re, float* im, int t) {
    stage0<INV>(re, im, t); __syncthreads();
    stage<INV, 1>(re, im, t); __syncthreads();
    stage<INV, 2>(re, im, t); __syncthreads();
    stage<INV, 3>(re, im, t); __syncthreads();
}

// ---------------------------------------------------------------------------
// Kernel A: squash + rfft(8192) -> fused pointwise table g_Tab (1/NC folded)
//   z'[k] = A Zk + B conj(Zj);  z'[j] = A' Zj + B' conj(Zk),  j = (NC-k)&4095
//   A  = [Kk(1+s) + conj(Kj)(1-s)]/2          s = sin(-pi k/NC)
//   B  =  i c [Kk - conj(Kj)]/2               c = cos(-pi k/NC)
//   A' = [Kj(1+s) + conj(Kk)(1-s)]/2
//   B' = -i c [Kj - conj(Kk)]/2
// ---------------------------------------------------------------------------
__global__ __launch_bounds__(512, 2) void build_kf_kernel(const float* __restrict__ kparam) {
    __shared__ float sre[SMSZ], sim[SMSZ];
    int t = threadIdx.x, h = blockIdx.x;
    const float2* kp2 = (const float2*)(kparam + (size_t)h * Ll);
    for (int m = t; m < 2048; m += 512) {
        float2 v = kp2[m];
        float s0 = fabsf(v.x) - LAMBDA; float a = (s0 > 0.f) ? copysignf(s0, v.x) : 0.f;
        float s1 = fabsf(v.y) - LAMBDA; float b = (s1 > 0.f) ? copysignf(s1, v.y) : 0.f;
        int p = sidx(m); sre[p] = a; sim[p] = b;
    }
    for (int m = 2048 + t; m < 4096; m += 512) { int p = sidx(m); sre[p] = 0.f; sim[p] = 0.f; }
    __syncthreads();

    fft_full<false>(sre, sim, t);

    float4* tab = g_Tab + (size_t)h * 4098;
    const float scale = 1.0f / (float)NC;
    for (int k = t; k <= NC / 2; k += 512) {
        if (k == 0) {
            float2 Z0 = make_float2(sre[sidx(0)], sim[sidx(0)]);
            float K0 = (Z0.x + Z0.y) * scale;
            float KN = (Z0.x - Z0.y) * scale;
            float4 e = make_float4(0.5f * (K0 + KN), 0.f, 0.f, 0.5f * (K0 - KN));
            tab[0] = e; tab[1] = e;                 // A'=A, B'=B (self-pair)
        } else if (k == NC / 2) {
            int p = sidx(NC / 2);
            // A = conj(K) = Z*scale, B = 0 (self-pair)
            float4 e = make_float4(sre[p] * scale, sim[p] * scale, 0.f, 0.f);
            tab[2 * k] = e; tab[2 * k + 1] = e;
        } else {
            int j = NC - k;
            int pk = sidx(k), pj = sidx(j);
            float2 Zk = make_float2(sre[pk], sim[pk]);
            float2 Zj = make_float2(sre[pj], sim[pj]);
            float2 E = make_float2(0.5f * (Zk.x + Zj.x),  0.5f * (Zk.y - Zj.y));
            float2 O = make_float2(0.5f * (Zk.y + Zj.y), -0.5f * (Zk.x - Zj.x));
            float sv, cv; __sincosf(-3.14159265358979f * (float)k / (float)NC, &sv, &cv);
            float2 W  = make_float2(cv, sv);
            float2 Wj = make_float2(-cv, sv);
            float2 Kk = cscale(cadd(E, cmul(W, O)), scale);
            float2 Kj = cscale(cadd(conjf2(E), cmul(Wj, conjf2(O))), scale);
            float s = sv, c = cv;
            float4 tA, tB;
            // A = 0.5[(1+s)Kk + (1-s)conj(Kj)], B = 0.5*i*c*(Kk - conj(Kj))
            tA.x = 0.5f * ((1.f + s) * Kk.x + (1.f - s) * Kj.x);
            tA.y = 0.5f * ((1.f + s) * Kk.y - (1.f - s) * Kj.y);
            tA.z = -0.5f * c * (Kk.y + Kj.y);
            tA.w =  0.5f * c * (Kk.x - Kj.x);
            // A' = 0.5[(1+s)Kj + (1-s)conj(Kk)], B' = -0.5*i*c*(Kj - conj(Kk))
            tB.x = 0.5f * ((1.f + s) * Kj.x + (1.f - s) * Kk.x);
            tB.y = 0.5f * ((1.f + s) * Kj.y - (1.f - s) * Kk.y);
            tB.z =  0.5f * c * (Kj.y + Kk.y);
            tB.w = -0.5f * c * (Kj.x - Kk.x);
            tab[2 * k]     = tA;
            tab[2 * k + 1] = tB;
        }
    }
}

// ---------------------------------------------------------------------------
// Kernel A2: W fp32 -> bf16 hi/lo split (done once, reused by all GEMM CTAs)
// ---------------------------------------------------------------------------
__global__ void split_w_kernel(const float* __restrict__ W) {
    int i = blockIdx.x * 256 + threadIdx.x;      // 65536 lanes, 4 floats each
    float4 w4 = *(const float4*)(W + 4 * (size_t)i);
    __nv_bfloat16 h0 = __float2bfloat16(w4.x);
    __nv_bfloat16 h1 = __float2bfloat16(w4.y);
    __nv_bfloat16 h2 = __float2bfloat16(w4.z);
    __nv_bfloat16 h3 = __float2bfloat16(w4.w);
    __nv_bfloat16 q0 = __float2bfloat16(w4.x - __bfloat162float(h0));
    __nv_bfloat16 q1 = __float2bfloat16(w4.y - __bfloat162float(h1));
    __nv_bfloat16 q2 = __float2bfloat16(w4.z - __bfloat162float(h2));
    __nv_bfloat16 q3 = __float2bfloat16(w4.w - __bfloat162float(h3));
    uint2 hp, lp;
    hp.x = (uint32_t)__bfloat16_as_ushort(h0) | ((uint32_t)__bfloat16_as_ushort(h1) << 16);
    hp.y = (uint32_t)__bfloat16_as_ushort(h2) | ((uint32_t)__bfloat16_as_ushort(h3) << 16);
    lp.x = (uint32_t)__bfloat16_as_ushort(q0) | ((uint32_t)__bfloat16_as_ushort(q1) << 16);
    lp.y = (uint32_t)__bfloat16_as_ushort(q2) | ((uint32_t)__bfloat16_as_ushort(q3) << 16);
    *(uint2*)(g_Whi + 2 * (size_t)i) = hp;
    *(uint2*)(g_Wlo + 2 * (size_t)i) = lp;
}

// ---------------------------------------------------------------------------
// Kernel B: rfft(u) -> fused table pointwise -> irfft -> +D*u -> GELU -> bf16 hi/lo
// ---------------------------------------------------------------------------
__global__ __launch_bounds__(512, 3) void conv_kernel(const float* __restrict__ u,
                                                      const float* __restrict__ D) {
    __shared__ float sre[SMSZ], sim[SMSZ];
    int t = threadIdx.x, h = blockIdx.x, b = blockIdx.y;
    const float2* u2 = (const float2*)(u + ((size_t)(b * Hh + h)) * Ll);

    for (int m = t; m < 2048; m += 512) { float2 v = u2[m]; int p = sidx(m); sre[p] = v.x; sim[p] = v.y; }
    for (int m = 2048 + t; m < 4096; m += 512) { int p = sidx(m); sre[p] = 0.f; sim[p] = 0.f; }
    __syncthreads();

    fft_full<false>(sre, sim, t);

    // fused pointwise via precomputed table
    const float4* tab = g_Tab + (size_t)h * 4098;
    for (int k = t; k <= NC / 2; k += 512) {
        int j = (NC - k) & (NC - 1);
        int pk = sidx(k), pj = sidx(j);
        float2 Zk = make_float2(sre[pk], sim[pk]);
        float2 Zj = make_float2(sre[pj], sim[pj]);
        float4 tA = tab[2 * k];
        float4 tB = tab[2 * k + 1];
        // z'[k] = A*Zk + B*conj(Zj)
        float nkx = tA.x * Zk.x - tA.y * Zk.y + tA.z * Zj.x + tA.w * Zj.y;
        float nky = tA.x * Zk.y + tA.y * Zk.x + tA.w * Zj.x - tA.z * Zj.y;
        // z'[j] = A'*Zj + B'*conj(Zk)
        float njx = tB.x * Zj.x - tB.y * Zj.y + tB.z * Zk.x + tB.w * Zk.y;
        float njy = tB.x * Zj.y + tB.y * Zj.x + tB.w * Zk.x - tB.z * Zk.y;
        sre[pk] = nkx; sim[pk] = nky;
        sre[pj] = njx; sim[pj] = njy;
    }
    __syncthreads();

    stage0<true>(sre, sim, t); __syncthreads();
    stage<true, 1>(sre, sim, t); __syncthreads();
    stage<true, 2>(sre, sim, t); __syncthreads();
    float2 a[8];
    stage3_reg<true>(sre, sim, t, a);

    float dcoef = D[h];
    uint32_t* yh = g_Yhi + ((size_t)(b * Hh + h)) * (Ll / 2);
    uint32_t* yl = g_Ylo + ((size_t)(b * Hh + h)) * (Ll / 2);
    const float INV_SQRT2 = 0.70710678118654752f;
#pragma unroll
    for (int i = 0; i < 4; i++) {
        int n = t + 512 * i;
        float2 uv = u2[n];
        float y0 = a[i].x + dcoef * uv.x;
        float y1 = a[i].y + dcoef * uv.y;
        y0 = 0.5f * y0 * (1.0f + erff(y0 * INV_SQRT2));
        y1 = 0.5f * y1 * (1.0f + erff(y1 * INV_SQRT2));
        __nv_bfloat16 h0 = __float2bfloat16(y0);
        __nv_bfloat16 h1 = __float2bfloat16(y1);
        float r0 = y0 - __bfloat162float(h0);
        float r1 = y1 - __bfloat162float(h1);
        __nv_bfloat16 l0b = __float2bfloat16(r0);
        __nv_bfloat16 l1b = __float2bfloat16(r1);
        yh[n] = (uint32_t)__bfloat16_as_ushort(h0) | ((uint32_t)__bfloat16_as_ushort(h1) << 16);
        yl[n] = (uint32_t)__bfloat16_as_ushort(l0b) | ((uint32_t)__bfloat16_as_ushort(l1b) << 16);
    }
}

// ---------------------------------------------------------------------------
// Kernel C: warp-MMA (HMMA) bf16 GEMM, 3-term precision split, bias + SiLU.
// CTA 128(v) x 128(l), K chunks of 64. 8 warps, warp tile 64x32.
// A smem: [128 rows][64 k] bf16, row stride 144B. B smem: [64 k][128 l], swizzled.
// ---------------------------------------------------------------------------
#define AK 64
#define ASTRIDE 144
#define OFF_AHI 0
#define OFF_ALO (128 * ASTRIDE)
#define OFF_BHI (2 * 128 * ASTRIDE)
#define OFF_BLO (OFF_BHI + 64 * 256)
#define GEMM_SMEM (OFF_BLO + 64 * 256)   // 69632 bytes

__device__ __forceinline__ uint32_t smem_u32(const void* p) {
    uint32_t a;
    asm("{ .reg .u64 t; cvta.to.shared.u64 t, %1; cvt.u32.u64 %0, t; }" : "=r"(a) : "l"(p));
    return a;
}
__device__ __forceinline__ void ldsm4(uint32_t r[4], uint32_t addr) {
    asm volatile("ldmatrix.sync.aligned.m8n8.x4.shared.b16 {%0,%1,%2,%3}, [%4];"
                 : "=r"(r[0]), "=r"(r[1]), "=r"(r[2]), "=r"(r[3]) : "r"(addr));
}
__device__ __forceinline__ void ldsm4t(uint32_t r[4], uint32_t addr) {
    asm volatile("ldmatrix.sync.aligned.m8n8.x4.trans.shared.b16 {%0,%1,%2,%3}, [%4];"
                 : "=r"(r[0]), "=r"(r[1]), "=r"(r[2]), "=r"(r[3]) : "r"(addr));
}
__device__ __forceinline__ void mma16816(float c[4], const uint32_t a[4], const uint32_t b[2]) {
    asm volatile(
        "mma.sync.aligned.m16n8k16.row.col.f32.bf16.bf16.f32 "
        "{%0,%1,%2,%3}, {%4,%5,%6,%7}, {%8,%9}, {%0,%1,%2,%3};"
        : "+f"(c[0]), "+f"(c[1]), "+f"(c[2]), "+f"(c[3])
        : "r"(a[0]), "r"(a[1]), "r"(a[2]), "r"(a[3]), "r"(b[0]), "r"(b[1]));
}
__device__ __forceinline__ float silu_f(float x) { return x / (1.0f + __expf(-x)); }
__device__ __forceinline__ int bswz(int k, int cb) { return (cb & 8) | ((cb ^ k) & 7); }

__global__ __launch_bounds__(256, 2) void gemm_silu_kernel(const float* __restrict__ bias,
                                                           float* __restrict__ out) {
    extern __shared__ char smem[];
    uint32_t sb = smem_u32(smem);
    int tid = threadIdx.x;
    int wid = tid >> 5;
    int lane = tid & 31;

    int v0 = blockIdx.x * 128;           // vt fastest -> 4 CTAs share B tile in L2
    int l0 = blockIdx.y * 128;
    int b  = blockIdx.z;

    int wm = wid & 1;
    int wn = wid >> 1;

    const __nv_bfloat16* Yh = (const __nv_bfloat16*)g_Yhi;
    const __nv_bfloat16* Yl = (const __nv_bfloat16*)g_Ylo;
    const __nv_bfloat16* Wh = (const __nv_bfloat16*)g_Whi;
    const __nv_bfloat16* Wl = (const __nv_bfloat16*)g_Wlo;

    float acc[4][4][4];
#pragma unroll
    for (int i = 0; i < 4; i++)
#pragma unroll
        for (int j = 0; j < 4; j++)
#pragma unroll
            for (int q = 0; q < 4; q++) acc[i][j][q] = 0.f;

    for (int c = 0; c < 8; c++) {
        int k0 = c * AK;

        // ---- load A tile (pre-split bf16): rows v0..v0+127, cols k0..k0+63
        {
            int r = tid >> 1;
            int half = tid & 1;
            size_t ga = (size_t)(v0 + r) * Hh + k0 + half * 32;
            char* ah = smem + OFF_AHI + r * ASTRIDE + half * 64;
            char* al = smem + OFF_ALO + r * ASTRIDE + half * 64;
#pragma unroll
            for (int i = 0; i < 4; i++) {
                *(uint4*)(ah + 16 * i) = *(const uint4*)(Wh + ga + 8 * i);
                *(uint4*)(al + 16 * i) = *(const uint4*)(Wl + ga + 8 * i);
            }
        }

        // ---- load B tile: Y[k0+k][l0..l0+127] (16B chunks, swizzled store)
        {
            int cb = tid & 15;
#pragma unroll
            for (int i = 0; i < 4; i++) {
                int k = (tid >> 4) + 16 * i;
                size_t ge = ((size_t)(b * Hh) + k0 + k) * Ll + l0 + cb * 8;
                uint4 vh = *(const uint4*)(Yh + ge);
                uint4 vl = *(const uint4*)(Yl + ge);
                int so = k * 256 + bswz(k, cb) * 16;
                *(uint4*)(smem + OFF_BHI + so) = vh;
                *(uint4*)(smem + OFF_BLO + so) = vl;
            }
        }
        __syncthreads();

#pragma unroll
        for (int ks = 0; ks < 4; ks++) {
            uint32_t bh[2][4], bl[2][4];
#pragma unroll
            for (int g = 0; g < 2; g++) {
                int krow = ks * 16 + (lane & 15);
                int cb = (wn * 32 + g * 16) / 8 + (lane >> 4);
                uint32_t baddr = sb + OFF_BHI + krow * 256 + bswz(krow, cb) * 16;
                ldsm4t(bh[g], baddr);
                ldsm4t(bl[g], baddr + (OFF_BLO - OFF_BHI));
            }
#pragma unroll
            for (int mt = 0; mt < 4; mt++) {
                int arow = wm * 64 + mt * 16 + (lane & 15);
                uint32_t aaddr = sb + OFF_AHI + arow * ASTRIDE + ks * 32 + (lane >> 4) * 16;
                uint32_t ahf[4], alf[4];
                ldsm4(ahf, aaddr);
                ldsm4(alf, aaddr + (uint32_t)(OFF_ALO - OFF_AHI));
#pragma unroll
                for (int nt = 0; nt < 4; nt++) {
                    const uint32_t* bhx = &bh[nt >> 1][(nt & 1) * 2];
                    const uint32_t* blx = &bl[nt >> 1][(nt & 1) * 2];
                    mma16816(acc[mt][nt], ahf, bhx);
                    mma16816(acc[mt][nt], ahf, blx);
                    mma16816(acc[mt][nt], alf, bhx);
                }
            }
        }
        __syncthreads();
    }

    int g = lane >> 2;
    int cq = (lane & 3) * 2;
#pragma unroll
    for (int mt = 0; mt < 4; mt++) {
        int vbase = v0 + wm * 64 + mt * 16 + g;
        float bv0 = bias[vbase];
        float bv1 = bias[vbase + 8];
        float* row0 = out + ((size_t)(b * Hh) + vbase) * Ll;
        float* row1 = row0 + 8 * Ll;
#pragma unroll
        for (int nt = 0; nt < 4; nt++) {
            int lc = l0 + wn * 32 + nt * 8 + cq;
            float2 o0, o1;
            o0.x = silu_f(acc[mt][nt][0] + bv0);
            o0.y = silu_f(acc[mt][nt][1] + bv0);
            o1.x = silu_f(acc[mt][nt][2] + bv1);
            o1.y = silu_f(acc[mt][nt][3] + bv1);
            *(float2*)(row0 + lc) = o0;
            *(float2*)(row1 + lc) = o1;
        }
    }
}

extern "C" void kernel_launch(void* const* d_in, const int* in_sizes, int n_in,
                              void* d_out, int out_size) {
    const float* u    = (const float*)d_in[0];   // (16, 512, 4096)
    const float* kern = (const float*)d_in[1];   // (1, 512, 4096)
    const float* D    = (const float*)d_in[2];   // (1, 512)
    const float* Wout = (const float*)d_in[3];   // (512, 512)
    const float* bout = (const float*)d_in[4];   // (512,)
    float* out = (float*)d_out;                  // (16, 512, 4096)

    cudaFuncSetAttribute(gemm_silu_kernel, cudaFuncAttributeMaxDynamicSharedMemorySize, GEMM_SMEM);

    build_kf_kernel<<<Hh, 512>>>(kern);
    split_w_kernel<<<256, 256>>>(Wout);
    conv_kernel<<<dim3(Hh, Bb), 512>>>(u, D);
    gemm_silu_kernel<<<dim3(4, 32, 16), 256, GEMM_SMEM>>>(bout, out);
}

// round 6
// speedup vs baseline: 3.6544x; 1.1673x over previous
#include <cuda_runtime.h>
#include <cuda_bf16.h>
#include <math.h>
#include <stdint.h>

#define Bb 16
#define Hh 512
#define Ll 4096
#define NC 4096
#define LAMBDA 0.001f

// Scratch (no runtime allocation allowed)
__device__ float4   g_Tab[(size_t)Hh * 4098];               // pointwise table per (h,k)
__device__ uint32_t g_Yhi[(size_t)Bb * Hh * Ll / 2];        // bf16x2 hi of gelu(conv+skip)
__device__ uint32_t g_Ylo[(size_t)Bb * Hh * Ll / 2];        // bf16x2 lo residual
__device__ uint32_t g_Whi[Hh * Hh / 2];                     // W bf16x2 hi, row-major [v][k]
__device__ uint32_t g_Wlo[Hh * Hh / 2];                     // W bf16x2 lo residual

__device__ __forceinline__ float2 cadd(float2 a, float2 b) { return make_float2(a.x + b.x, a.y + b.y); }
__device__ __forceinline__ float2 csub(float2 a, float2 b) { return make_float2(a.x - b.x, a.y - b.y); }
__device__ __forceinline__ float2 cmul(float2 a, float2 b) {
    return make_float2(a.x * b.x - a.y * b.y, a.x * b.y + a.y * b.x);
}
__device__ __forceinline__ float2 conjf2(float2 a) { return make_float2(a.x, -a.y); }
__device__ __forceinline__ float2 cscale(float2 a, float s) { return make_float2(a.x * s, a.y * s); }

__device__ __forceinline__ int sidx(int n) { return n + (n >> 4); }
#define SMSZ (4096 + 256)

// ---------------------------------------------------------------------------
// radix-8 FFT machinery on interleaved float2 shared array (LDS.64 path)
// ---------------------------------------------------------------------------
template <bool INV>
__device__ __forceinline__ void radix8(float2 a[8]) {
    const float C = 0.70710678118654752440f;
    float2 t0 = cadd(a[0], a[4]);
    float2 t1 = csub(a[0], a[4]);
    float2 t2 = cadd(a[2], a[6]);
    float2 t3;
    { float2 d = csub(a[2], a[6]); t3 = INV ? make_float2(-d.y, d.x) : make_float2(d.y, -d.x); }
    float2 E0 = cadd(t0, t2), E2 = csub(t0, t2);
    float2 E1 = cadd(t1, t3), E3 = csub(t1, t3);
    float2 s0 = cadd(a[1], a[5]);
    float2 s1 = csub(a[1], a[5]);
    float2 s2 = cadd(a[3], a[7]);
    float2 s3;
    { float2 d = csub(a[3], a[7]); s3 = INV ? make_float2(-d.y, d.x) : make_float2(d.y, -d.x); }
    float2 O0 = cadd(s0, s2), O2 = csub(s0, s2);
    float2 O1 = cadd(s1, s3), O3 = csub(s1, s3);
    float2 O1w, O2w, O3w;
    if (!INV) {
        O1w = make_float2(C * (O1.x + O1.y), C * (O1.y - O1.x));
        O2w = make_float2(O2.y, -O2.x);
        O3w = make_float2(C * (O3.y - O3.x), -C * (O3.x + O3.y));
    } else {
        O1w = make_float2(C * (O1.x - O1.y), C * (O1.y + O1.x));
        O2w = make_float2(-O2.y, O2.x);
        O3w = make_float2(-C * (O3.x + O3.y), C * (O3.x - O3.y));
    }
    a[0] = cadd(E0, O0);  a[4] = csub(E0, O0);
    a[1] = cadd(E1, O1w); a[5] = csub(E1, O1w);
    a[2] = cadd(E2, O2w); a[6] = csub(E2, O2w);
    a[3] = cadd(E3, O3w); a[7] = csub(E3, O3w);
}

template <bool INV>
__device__ __forceinline__ void stage0(float2* z, int t) {
    int r3 = ((t & 7) << 6) | (t & 56) | (t >> 6);
    float2 a[8];
#pragma unroll
    for (int i = 0; i < 8; i++) a[i] = z[sidx(i * 512 + r3)];
    __syncthreads();
    radix8<INV>(a);
#pragma unroll
    for (int i = 0; i < 8; i++) z[sidx(8 * t + i)] = a[i];
}

template <bool INV, int S>
__device__ __forceinline__ void stage(float2* z, int t) {
    constexpr int ST = 1 << (3 * S);
    constexpr int M8 = ST * 8;
    int j = t & (ST - 1);
    int base = ((t >> (3 * S)) << (3 * (S + 1))) + j;
    float2 a[8];
#pragma unroll
    for (int i = 0; i < 8; i++) a[i] = z[sidx(base + i * ST)];
    if (j) {
        float ang = (INV ? 6.283185307179586f : -6.283185307179586f) * (float)j / (float)M8;
        float sv, cv; __sincosf(ang, &sv, &cv);
        float2 w1 = make_float2(cv, sv), w = w1;
        a[1] = cmul(a[1], w);
#pragma unroll
        for (int i = 2; i < 8; i++) { w = cmul(w, w1); a[i] = cmul(a[i], w); }
    }
    radix8<INV>(a);
#pragma unroll
    for (int i = 0; i < 8; i++) z[sidx(base + i * ST)] = a[i];
}

template <bool INV>
__device__ __forceinline__ void stage3_reg(const float2* z, int t, float2 a[8]) {
#pragma unroll
    for (int i = 0; i < 8; i++) a[i] = z[sidx(t + i * 512)];
    if (t) {
        float ang = (INV ? 6.283185307179586f : -6.283185307179586f) * (float)t / 4096.0f;
        float sv, cv; __sincosf(ang, &sv, &cv);
        float2 w1 = make_float2(cv, sv), w = w1;
        a[1] = cmul(a[1], w);
#pragma unroll
        for (int i = 2; i < 8; i++) { w = cmul(w, w1); a[i] = cmul(a[i], w); }
    }
    radix8<INV>(a);
}

template <bool INV>
__device__ __forceinline__ void fft_full(float2* z, int t) {
    stage0<INV>(z, t); __syncthreads();
    stage<INV, 1>(z, t); __syncthreads();
    stage<INV, 2>(z, t); __syncthreads();
    stage<INV, 3>(z, t); __syncthreads();
}

// ---------------------------------------------------------------------------
// Kernel A: squash + rfft(8192) -> fused pointwise table g_Tab (1/NC folded)
// ---------------------------------------------------------------------------
__global__ __launch_bounds__(512, 2) void build_kf_kernel(const float* __restrict__ kparam) {
    __shared__ float2 z[SMSZ];
    int t = threadIdx.x, h = blockIdx.x;
    const float2* kp2 = (const float2*)(kparam + (size_t)h * Ll);
    for (int m = t; m < 2048; m += 512) {
        float2 v = kp2[m];
        float s0 = fabsf(v.x) - LAMBDA; float a = (s0 > 0.f) ? copysignf(s0, v.x) : 0.f;
        float s1 = fabsf(v.y) - LAMBDA; float b = (s1 > 0.f) ? copysignf(s1, v.y) : 0.f;
        z[sidx(m)] = make_float2(a, b);
    }
    for (int m = 2048 + t; m < 4096; m += 512) z[sidx(m)] = make_float2(0.f, 0.f);
    __syncthreads();

    fft_full<false>(z, t);

    float4* tab = g_Tab + (size_t)h * 4098;
    const float scale = 1.0f / (float)NC;
    for (int k = t; k <= NC / 2; k += 512) {
        if (k == 0) {
            float2 Z0 = z[sidx(0)];
            float K0 = (Z0.x + Z0.y) * scale;
            float KN = (Z0.x - Z0.y) * scale;
            float4 e = make_float4(0.5f * (K0 + KN), 0.f, 0.f, 0.5f * (K0 - KN));
            tab[0] = e; tab[1] = e;
        } else if (k == NC / 2) {
            float2 Zm = z[sidx(NC / 2)];
            float4 e = make_float4(Zm.x * scale, Zm.y * scale, 0.f, 0.f);
            tab[2 * k] = e; tab[2 * k + 1] = e;
        } else {
            int j = NC - k;
            float2 Zk = z[sidx(k)];
            float2 Zj = z[sidx(j)];
            float2 E = make_float2(0.5f * (Zk.x + Zj.x),  0.5f * (Zk.y - Zj.y));
            float2 O = make_float2(0.5f * (Zk.y + Zj.y), -0.5f * (Zk.x - Zj.x));
            float sv, cv; __sincosf(-3.14159265358979f * (float)k / (float)NC, &sv, &cv);
            float2 W  = make_float2(cv, sv);
            float2 Wj = make_float2(-cv, sv);
            float2 Kk = cscale(cadd(E, cmul(W, O)), scale);
            float2 Kj = cscale(cadd(conjf2(E), cmul(Wj, conjf2(O))), scale);
            float s = sv, c = cv;
            float4 tA, tB;
            tA.x = 0.5f * ((1.f + s) * Kk.x + (1.f - s) * Kj.x);
            tA.y = 0.5f * ((1.f + s) * Kk.y - (1.f - s) * Kj.y);
            tA.z = -0.5f * c * (Kk.y + Kj.y);
            tA.w =  0.5f * c * (Kk.x - Kj.x);
            tB.x = 0.5f * ((1.f + s) * Kj.x + (1.f - s) * Kk.x);
            tB.y = 0.5f * ((1.f + s) * Kj.y - (1.f - s) * Kk.y);
            tB.z =  0.5f * c * (Kj.y + Kk.y);
            tB.w = -0.5f * c * (Kj.x - Kk.x);
            tab[2 * k]     = tA;
            tab[2 * k + 1] = tB;
        }
    }
}

// ---------------------------------------------------------------------------
// Kernel A2: W fp32 -> bf16 hi/lo split (done once)
// ---------------------------------------------------------------------------
__global__ void split_w_kernel(const float* __restrict__ W) {
    int i = blockIdx.x * 256 + threadIdx.x;
    float4 w4 = *(const float4*)(W + 4 * (size_t)i);
    __nv_bfloat16 h0 = __float2bfloat16(w4.x);
    __nv_bfloat16 h1 = __float2bfloat16(w4.y);
    __nv_bfloat16 h2 = __float2bfloat16(w4.z);
    __nv_bfloat16 h3 = __float2bfloat16(w4.w);
    __nv_bfloat16 q0 = __float2bfloat16(w4.x - __bfloat162float(h0));
    __nv_bfloat16 q1 = __float2bfloat16(w4.y - __bfloat162float(h1));
    __nv_bfloat16 q2 = __float2bfloat16(w4.z - __bfloat162float(h2));
    __nv_bfloat16 q3 = __float2bfloat16(w4.w - __bfloat162float(h3));
    uint2 hp, lp;
    hp.x = (uint32_t)__bfloat16_as_ushort(h0) | ((uint32_t)__bfloat16_as_ushort(h1) << 16);
    hp.y = (uint32_t)__bfloat16_as_ushort(h2) | ((uint32_t)__bfloat16_as_ushort(h3) << 16);
    lp.x = (uint32_t)__bfloat16_as_ushort(q0) | ((uint32_t)__bfloat16_as_ushort(q1) << 16);
    lp.y = (uint32_t)__bfloat16_as_ushort(q2) | ((uint32_t)__bfloat16_as_ushort(q3) << 16);
    *(uint2*)(g_Whi + 2 * (size_t)i) = hp;
    *(uint2*)(g_Wlo + 2 * (size_t)i) = lp;
}

// ---------------------------------------------------------------------------
// Kernel B: rfft(u) -> table pointwise -> irfft -> +D*u -> GELU -> bf16 hi/lo
// ---------------------------------------------------------------------------
__global__ __launch_bounds__(512, 3) void conv_kernel(const float* __restrict__ u,
                                                      const float* __restrict__ D) {
    __shared__ float2 z[SMSZ];
    int t = threadIdx.x, h = blockIdx.x, b = blockIdx.y;
    const float2* u2 = (const float2*)(u + ((size_t)(b * Hh + h)) * Ll);

    for (int m = t; m < 2048; m += 512) z[sidx(m)] = u2[m];
    for (int m = 2048 + t; m < 4096; m += 512) z[sidx(m)] = make_float2(0.f, 0.f);
    __syncthreads();

    fft_full<false>(z, t);

    const float4* tab = g_Tab + (size_t)h * 4098;
    for (int k = t; k <= NC / 2; k += 512) {
        int j = (NC - k) & (NC - 1);
        int pk = sidx(k), pj = sidx(j);
        float2 Zk = z[pk];
        float2 Zj = z[pj];
        float4 tA = tab[2 * k];
        float4 tB = tab[2 * k + 1];
        float nkx = tA.x * Zk.x - tA.y * Zk.y + tA.z * Zj.x + tA.w * Zj.y;
        float nky = tA.x * Zk.y + tA.y * Zk.x + tA.w * Zj.x - tA.z * Zj.y;
        float njx = tB.x * Zj.x - tB.y * Zj.y + tB.z * Zk.x + tB.w * Zk.y;
        float njy = tB.x * Zj.y + tB.y * Zj.x + tB.w * Zk.x - tB.z * Zk.y;
        z[pk] = make_float2(nkx, nky);
        z[pj] = make_float2(njx, njy);
    }
    __syncthreads();

    stage0<true>(z, t); __syncthreads();
    stage<true, 1>(z, t); __syncthreads();
    stage<true, 2>(z, t); __syncthreads();
    float2 a[8];
    stage3_reg<true>(z, t, a);

    float dcoef = D[h];
    uint32_t* yh = g_Yhi + ((size_t)(b * Hh + h)) * (Ll / 2);
    uint32_t* yl = g_Ylo + ((size_t)(b * Hh + h)) * (Ll / 2);
    const float INV_SQRT2 = 0.70710678118654752f;
#pragma unroll
    for (int i = 0; i < 4; i++) {
        int n = t + 512 * i;
        float2 uv = u2[n];
        float y0 = a[i].x + dcoef * uv.x;
        float y1 = a[i].y + dcoef * uv.y;
        y0 = 0.5f * y0 * (1.0f + erff(y0 * INV_SQRT2));
        y1 = 0.5f * y1 * (1.0f + erff(y1 * INV_SQRT2));
        __nv_bfloat16 h0 = __float2bfloat16(y0);
        __nv_bfloat16 h1 = __float2bfloat16(y1);
        float r0 = y0 - __bfloat162float(h0);
        float r1 = y1 - __bfloat162float(h1);
        __nv_bfloat16 l0b = __float2bfloat16(r0);
        __nv_bfloat16 l1b = __float2bfloat16(r1);
        yh[n] = (uint32_t)__bfloat16_as_ushort(h0) | ((uint32_t)__bfloat16_as_ushort(h1) << 16);
        yl[n] = (uint32_t)__bfloat16_as_ushort(l0b) | ((uint32_t)__bfloat16_as_ushort(l1b) << 16);
    }
}

// ---------------------------------------------------------------------------
// Kernel C: HMMA bf16 GEMM, 3-term split, cp.async 2-stage pipeline (k=32),
// CTA 128x128, 8 warps (warp 64x32), bias + SiLU epilogue.
// ---------------------------------------------------------------------------
#define HC 32
#define NHC 16
#define A_ST 80
// per-stage: Ahi 10240 | Alo 10240 | Bhi 8192 | Blo 8192 = 36864
#define ST_SZ 36864
#define GEMM_SMEM (2 * ST_SZ)   // 73728

__device__ __forceinline__ uint32_t smem_u32(const void* p) {
    uint32_t a;
    asm("{ .reg .u64 t; cvta.to.shared.u64 t, %1; cvt.u32.u64 %0, t; }" : "=r"(a) : "l"(p));
    return a;
}
__device__ __forceinline__ void cpa16(uint32_t dst, const void* src) {
    asm volatile("cp.async.cg.shared.global [%0], [%1], 16;" :: "r"(dst), "l"(src));
}
__device__ __forceinline__ void ldsm4(uint32_t r[4], uint32_t addr) {
    asm volatile("ldmatrix.sync.aligned.m8n8.x4.shared.b16 {%0,%1,%2,%3}, [%4];"
                 : "=r"(r[0]), "=r"(r[1]), "=r"(r[2]), "=r"(r[3]) : "r"(addr));
}
__device__ __forceinline__ void ldsm4t(uint32_t r[4], uint32_t addr) {
    asm volatile("ldmatrix.sync.aligned.m8n8.x4.trans.shared.b16 {%0,%1,%2,%3}, [%4];"
                 : "=r"(r[0]), "=r"(r[1]), "=r"(r[2]), "=r"(r[3]) : "r"(addr));
}
__device__ __forceinline__ void mma16816(float c[4], const uint32_t a[4], const uint32_t b[2]) {
    asm volatile(
        "mma.sync.aligned.m16n8k16.row.col.f32.bf16.bf16.f32 "
        "{%0,%1,%2,%3}, {%4,%5,%6,%7}, {%8,%9}, {%0,%1,%2,%3};"
        : "+f"(c[0]), "+f"(c[1]), "+f"(c[2]), "+f"(c[3])
        : "r"(a[0]), "r"(a[1]), "r"(a[2]), "r"(a[3]), "r"(b[0]), "r"(b[1]));
}
__device__ __forceinline__ float silu_f(float x) { return x / (1.0f + __expf(-x)); }
__device__ __forceinline__ int bswz(int k, int cb) { return (cb & 8) | ((cb ^ k) & 7); }

__global__ __launch_bounds__(256, 2) void gemm_silu_kernel(const float* __restrict__ bias,
                                                           float* __restrict__ out) {
    extern __shared__ char smem[];
    uint32_t sb = smem_u32(smem);
    int tid = threadIdx.x;
    int wid = tid >> 5;
    int lane = tid & 31;

    int v0 = blockIdx.x * 128;           // vt fastest -> 4 CTAs share B tile in L2
    int l0 = blockIdx.y * 128;
    int b  = blockIdx.z;

    int wm = wid & 1;
    int wn = wid >> 1;

    const __nv_bfloat16* Yh = (const __nv_bfloat16*)g_Yhi;
    const __nv_bfloat16* Yl = (const __nv_bfloat16*)g_Ylo;
    const __nv_bfloat16* Wh = (const __nv_bfloat16*)g_Whi;
    const __nv_bfloat16* Wl = (const __nv_bfloat16*)g_Wlo;

    float acc[4][4][4];
#pragma unroll
    for (int i = 0; i < 4; i++)
#pragma unroll
        for (int j = 0; j < 4; j++)
#pragma unroll
            for (int q = 0; q < 4; q++) acc[i][j][q] = 0.f;

    // per-thread load slots (fixed across chunks, only k0 varies)
    int ar  = tid >> 2;                  // A row pair base: 2 rows per thread (q, q+256)
    int abk = tid & 3;                   // 16B block within 64B k-span
    int bk  = tid >> 4;                  // B k-row base (q, q+256 -> +16)
    int bcb = tid & 15;                  // B 16B block in 256B row

    // issue cp.async loads for half-chunk hc into stage s
    auto load_hc = [&](int hc, int s) {
        int k0 = hc * HC;
        uint32_t base = sb + s * ST_SZ;
        // A hi/lo: 128 rows x 32k: rows r and r+64
#pragma unroll
        for (int g = 0; g < 2; g++) {
            int r = ar + g * 64;
            size_t ga = (size_t)(v0 + r) * Hh + k0 + abk * 8;
            uint32_t da = base + r * A_ST + abk * 16;
            cpa16(da,         Wh + ga);
            cpa16(da + 10240, Wl + ga);
        }
        // B hi/lo: 32 k-rows x 128n: rows bk and bk+16
#pragma unroll
        for (int g = 0; g < 2; g++) {
            int k = bk + g * 16;
            size_t ge = ((size_t)(b * Hh) + k0 + k) * Ll + l0 + bcb * 8;
            uint32_t db = base + 20480 + k * 256 + bswz(k, bcb) * 16;
            cpa16(db,        Yh + ge);
            cpa16(db + 8192, Yl + ge);
        }
    };

    load_hc(0, 0);
    asm volatile("cp.async.commit_group;" ::: "memory");

    for (int hc = 0; hc < NHC; hc++) {
        int s = hc & 1;
        if (hc + 1 < NHC) {
            load_hc(hc + 1, (hc + 1) & 1);
            asm volatile("cp.async.commit_group;" ::: "memory");
            asm volatile("cp.async.wait_group 1;" ::: "memory");
        } else {
            asm volatile("cp.async.wait_group 0;" ::: "memory");
        }
        __syncthreads();

        uint32_t abase = sb + s * ST_SZ;
        uint32_t bbase = abase + 20480;
#pragma unroll
        for (int ks = 0; ks < 2; ks++) {
            uint32_t bh[2][4], bl[2][4];
#pragma unroll
            for (int g = 0; g < 2; g++) {
                int krow = ks * 16 + (lane & 15);
                int cb = wn * 4 + g * 2 + (lane >> 4);
                uint32_t baddr = bbase + krow * 256 + bswz(krow, cb) * 16;
                ldsm4t(bh[g], baddr);
                ldsm4t(bl[g], baddr + 8192);
            }
#pragma unroll
            for (int mt = 0; mt < 4; mt++) {
                int arow = wm * 64 + mt * 16 + (lane & 15);
                uint32_t aaddr = abase + arow * A_ST + ks * 32 + (lane >> 4) * 16;
                uint32_t ahf[4], alf[4];
                ldsm4(ahf, aaddr);
                ldsm4(alf, aaddr + 10240);
#pragma unroll
                for (int nt = 0; nt < 4; nt++) {
                    const uint32_t* bhx = &bh[nt >> 1][(nt & 1) * 2];
                    const uint32_t* blx = &bl[nt >> 1][(nt & 1) * 2];
                    mma16816(acc[mt][nt], ahf, bhx);
                    mma16816(acc[mt][nt], ahf, blx);
                    mma16816(acc[mt][nt], alf, bhx);
                }
            }
        }
        __syncthreads();
    }

    int g = lane >> 2;
    int cq = (lane & 3) * 2;
#pragma unroll
    for (int mt = 0; mt < 4; mt++) {
        int vbase = v0 + wm * 64 + mt * 16 + g;
        float bv0 = bias[vbase];
        float bv1 = bias[vbase + 8];
        float* row0 = out + ((size_t)(b * Hh) + vbase) * Ll;
        float* row1 = row0 + 8 * Ll;
#pragma unroll
        for (int nt = 0; nt < 4; nt++) {
            int lc = l0 + wn * 32 + nt * 8 + cq;
            float2 o0, o1;
            o0.x = silu_f(acc[mt][nt][0] + bv0);
            o0.y = silu_f(acc[mt][nt][1] + bv0);
            o1.x = silu_f(acc[mt][nt][2] + bv1);
            o1.y = silu_f(acc[mt][nt][3] + bv1);
            *(float2*)(row0 + lc) = o0;
            *(float2*)(row1 + lc) = o1;
        }
    }
}

extern "C" void kernel_launch(void* const* d_in, const int* in_sizes, int n_in,
                              void* d_out, int out_size) {
    const float* u    = (const float*)d_in[0];   // (16, 512, 4096)
    const float* kern = (const float*)d_in[1];   // (1, 512, 4096)
    const float* D    = (const float*)d_in[2];   // (1, 512)
    const float* Wout = (const float*)d_in[3];   // (512, 512)
    const float* bout = (const float*)d_in[4];   // (512,)
    float* out = (float*)d_out;                  // (16, 512, 4096)

    cudaFuncSetAttribute(gemm_silu_kernel, cudaFuncAttributeMaxDynamicSharedMemorySize, GEMM_SMEM);

    build_kf_kernel<<<Hh, 512>>>(kern);
    split_w_kernel<<<256, 256>>>(Wout);
    conv_kernel<<<dim3(Hh, Bb), 512>>>(u, D);
    gemm_silu_kernel<<<dim3(4, 32, 16), 256, GEMM_SMEM>>>(bout, out);
}

// round 7
// speedup vs baseline: 4.0942x; 1.1204x over previous
#include <cuda_runtime.h>
#include <cuda_bf16.h>
#include <math.h>
#include <stdint.h>

#define Bb 16
#define Hh 512
#define Ll 4096
#define NC 4096
#define LAMBDA 0.001f

// Scratch (no runtime allocation allowed)
__device__ float4   g_Tab[(size_t)Hh * 4096];               // per-POSITION pointwise table
__device__ uint32_t g_Yhi[(size_t)Bb * Hh * Ll / 2];        // bf16x2 hi of gelu(conv+skip)
__device__ uint32_t g_Ylo[(size_t)Bb * Hh * Ll / 2];        // bf16x2 lo residual
__device__ uint32_t g_Whi[Hh * Hh / 2];                     // W bf16x2 hi, row-major [v][k]
__device__ uint32_t g_Wlo[Hh * Hh / 2];                     // W bf16x2 lo residual

__device__ __forceinline__ float2 cadd(float2 a, float2 b) { return make_float2(a.x + b.x, a.y + b.y); }
__device__ __forceinline__ float2 csub(float2 a, float2 b) { return make_float2(a.x - b.x, a.y - b.y); }
__device__ __forceinline__ float2 cmul(float2 a, float2 b) {
    return make_float2(a.x * b.x - a.y * b.y, a.x * b.y + a.y * b.x);
}
__device__ __forceinline__ float2 conjf2(float2 a) { return make_float2(a.x, -a.y); }
__device__ __forceinline__ float2 cscale(float2 a, float s) { return make_float2(a.x * s, a.y * s); }

__device__ __forceinline__ int sidx(int n) { return n + (n >> 4); }
#define SMSZ (4096 + 256)

// 4-digit octal reversal (12-bit), involutive
__device__ __forceinline__ int rev4(int k) {
    return ((k & 7) << 9) | (((k >> 3) & 7) << 6) | (((k >> 6) & 7) << 3) | ((k >> 9) & 7);
}

// ---------------------------------------------------------------------------
// radix-8 butterfly (validated)
// ---------------------------------------------------------------------------
template <bool INV>
__device__ __forceinline__ void radix8(float2 a[8]) {
    const float C = 0.70710678118654752440f;
    float2 t0 = cadd(a[0], a[4]);
    float2 t1 = csub(a[0], a[4]);
    float2 t2 = cadd(a[2], a[6]);
    float2 t3;
    { float2 d = csub(a[2], a[6]); t3 = INV ? make_float2(-d.y, d.x) : make_float2(d.y, -d.x); }
    float2 E0 = cadd(t0, t2), E2 = csub(t0, t2);
    float2 E1 = cadd(t1, t3), E3 = csub(t1, t3);
    float2 s0 = cadd(a[1], a[5]);
    float2 s1 = csub(a[1], a[5]);
    float2 s2 = cadd(a[3], a[7]);
    float2 s3;
    { float2 d = csub(a[3], a[7]); s3 = INV ? make_float2(-d.y, d.x) : make_float2(d.y, -d.x); }
    float2 O0 = cadd(s0, s2), O2 = csub(s0, s2);
    float2 O1 = cadd(s1, s3), O3 = csub(s1, s3);
    float2 O1w, O2w, O3w;
    if (!INV) {
        O1w = make_float2(C * (O1.x + O1.y), C * (O1.y - O1.x));
        O2w = make_float2(O2.y, -O2.x);
        O3w = make_float2(C * (O3.y - O3.x), -C * (O3.x + O3.y));
    } else {
        O1w = make_float2(C * (O1.x - O1.y), C * (O1.y + O1.x));
        O2w = make_float2(-O2.y, O2.x);
        O3w = make_float2(-C * (O3.x + O3.y), C * (O3.x - O3.y));
    }
    a[0] = cadd(E0, O0);  a[4] = csub(E0, O0);
    a[1] = cadd(E1, O1w); a[5] = csub(E1, O1w);
    a[2] = cadd(E2, O2w); a[6] = csub(E2, O2w);
    a[3] = cadd(E3, O3w); a[7] = csub(E3, O3w);
}

__device__ __forceinline__ void twiddle8(float2 a[8], float ang) {
    float sv, cv; __sincosf(ang, &sv, &cv);
    float2 w1 = make_float2(cv, sv), w = w1;
    a[1] = cmul(a[1], w);
#pragma unroll
    for (int i = 2; i < 8; i++) { w = cmul(w, w1); a[i] = cmul(a[i], w); }
}

// In-place radix-8 stage. POST=true: DIF (twiddle after butterfly).
// POST=false: DIT (twiddle before). S = sub-stride; group size = 8S.
template <bool INV, int LOGS, bool POST>
__device__ __forceinline__ void stage_g(float2* z, int t) {
    constexpr int S = 1 << LOGS;
    int j = t & (S - 1);
    int base = ((t >> LOGS) << (LOGS + 3)) + j;
    float2 a[8];
#pragma unroll
    for (int i = 0; i < 8; i++) a[i] = z[sidx(base + i * S)];
    bool tw = (S > 1) && (j != 0);
    float ang = (INV ? 6.283185307179586f : -6.283185307179586f) * (float)j / (float)(8 * S);
    if (!POST && tw) twiddle8(a, ang);
    radix8<INV>(a);
    if (POST && tw) twiddle8(a, ang);
#pragma unroll
    for (int i = 0; i < 8; i++) z[sidx(base + i * S)] = a[i];
}

// Forward DIF first stage (S=512), input a[] already loaded (a[4..7]=0 upstream)
__device__ __forceinline__ void fwd_first_stage(float2* z, int t, float2 a[8]) {
    radix8<false>(a);
    if (t) twiddle8(a, -6.283185307179586f * (float)t / 4096.0f);
#pragma unroll
    for (int i = 0; i < 8; i++) z[sidx(t + i * 512)] = a[i];
}

// ---------------------------------------------------------------------------
// Kernel A: squash + DIF rfft(8192 packed) -> per-position table g_Tab
// position p holds packed-spectrum frequency k = rev4(p).
// ---------------------------------------------------------------------------
__global__ __launch_bounds__(512, 2) void build_kf_kernel(const float* __restrict__ kparam) {
    __shared__ float2 z[SMSZ];
    int t = threadIdx.x, h = blockIdx.x;
    const float2* kp2 = (const float2*)(kparam + (size_t)h * Ll);

    float2 a[8];
#pragma unroll
    for (int i = 0; i < 4; i++) {
        float2 v = kp2[t + 512 * i];
        float s0 = fabsf(v.x) - LAMBDA; float aa = (s0 > 0.f) ? copysignf(s0, v.x) : 0.f;
        float s1 = fabsf(v.y) - LAMBDA; float bb = (s1 > 0.f) ? copysignf(s1, v.y) : 0.f;
        a[i] = make_float2(aa, bb);
    }
#pragma unroll
    for (int i = 4; i < 8; i++) a[i] = make_float2(0.f, 0.f);
    fwd_first_stage(z, t, a);
    __syncthreads();
    stage_g<false, 6, true>(z, t); __syncthreads();
    stage_g<false, 3, true>(z, t); __syncthreads();
    stage_g<false, 0, true>(z, t); __syncthreads();

    float4* tab = g_Tab + (size_t)h * 4096;
    const float scale = 1.0f / (float)NC;
    for (int p = t; p < 4096; p += 512) {
        int k = rev4(p);
        float4 e;
        if (k == 0) {
            float2 Z0 = z[sidx(0)];
            float K0 = (Z0.x + Z0.y) * scale;
            float KN = (Z0.x - Z0.y) * scale;
            e = make_float4(0.5f * (K0 + KN), 0.f, 0.f, 0.5f * (K0 - KN));
        } else {
            int kk = (k <= 2048) ? k : 4096 - k;      // canonical index in [1,2048]
            float2 Zk = z[sidx(rev4(kk))];
            float2 Zj = z[sidx(rev4(4096 - kk))];
            float2 E = make_float2(0.5f * (Zk.x + Zj.x),  0.5f * (Zk.y - Zj.y));
            float2 O = make_float2(0.5f * (Zk.y + Zj.y), -0.5f * (Zk.x - Zj.x));
            float sv, cv; __sincosf(-3.14159265358979f * (float)kk / (float)NC, &sv, &cv);
            float2 W  = make_float2(cv, sv);
            float2 Wj = make_float2(-cv, sv);
            float2 Kk = cscale(cadd(E, cmul(W, O)), scale);            // freq kk
            float2 Kj = cscale(cadd(conjf2(E), cmul(Wj, conjf2(O))), scale); // freq 4096-kk
            float s = sv, c = cv;
            if (k <= 2048) {
                // A,B for frequency kk
                e.x = 0.5f * ((1.f + s) * Kk.x + (1.f - s) * Kj.x);
                e.y = 0.5f * ((1.f + s) * Kk.y - (1.f - s) * Kj.y);
                e.z = -0.5f * c * (Kk.y + Kj.y);
                e.w =  0.5f * c * (Kk.x - Kj.x);
            } else {
                // A',B' for frequency 4096-kk = k
                e.x = 0.5f * ((1.f + s) * Kj.x + (1.f - s) * Kk.x);
                e.y = 0.5f * ((1.f + s) * Kj.y - (1.f - s) * Kk.y);
                e.z =  0.5f * c * (Kj.y + Kk.y);
                e.w = -0.5f * c * (Kj.x - Kk.x);
            }
        }
        tab[p] = e;
    }
}

// ---------------------------------------------------------------------------
// Kernel A2: W fp32 -> bf16 hi/lo split (once)
// ---------------------------------------------------------------------------
__global__ void split_w_kernel(const float* __restrict__ W) {
    int i = blockIdx.x * 256 + threadIdx.x;
    float4 w4 = *(const float4*)(W + 4 * (size_t)i);
    __nv_bfloat16 h0 = __float2bfloat16(w4.x);
    __nv_bfloat16 h1 = __float2bfloat16(w4.y);
    __nv_bfloat16 h2 = __float2bfloat16(w4.z);
    __nv_bfloat16 h3 = __float2bfloat16(w4.w);
    __nv_bfloat16 q0 = __float2bfloat16(w4.x - __bfloat162float(h0));
    __nv_bfloat16 q1 = __float2bfloat16(w4.y - __bfloat162float(h1));
    __nv_bfloat16 q2 = __float2bfloat16(w4.z - __bfloat162float(h2));
    __nv_bfloat16 q3 = __float2bfloat16(w4.w - __bfloat162float(h3));
    uint2 hp, lp;
    hp.x = (uint32_t)__bfloat16_as_ushort(h0) | ((uint32_t)__bfloat16_as_ushort(h1) << 16);
    hp.y = (uint32_t)__bfloat16_as_ushort(h2) | ((uint32_t)__bfloat16_as_ushort(h3) << 16);
    lp.x = (uint32_t)__bfloat16_as_ushort(q0) | ((uint32_t)__bfloat16_as_ushort(q1) << 16);
    lp.y = (uint32_t)__bfloat16_as_ushort(q2) | ((uint32_t)__bfloat16_as_ushort(q3) << 16);
    *(uint2*)(g_Whi + 2 * (size_t)i) = hp;
    *(uint2*)(g_Wlo + 2 * (size_t)i) = lp;
}

// ---------------------------------------------------------------------------
// Kernel B: DIF fwd (global-fused 1st stage) -> per-position pointwise (z->z2)
//           -> DIT inverse (last stage in regs) -> +D*u -> GELU -> bf16 hi/lo
// ---------------------------------------------------------------------------
#define CONV_SMEM (2 * SMSZ * (int)sizeof(float2))   // 69632

__global__ __launch_bounds__(512, 3) void conv_kernel(const float* __restrict__ u,
                                                      const float* __restrict__ D) {
    extern __shared__ float2 zz[];
    float2* z  = zz;
    float2* z2 = zz + SMSZ;
    int t = threadIdx.x, h = blockIdx.x, b = blockIdx.y;
    const float2* u2 = (const float2*)(u + ((size_t)(b * Hh + h)) * Ll);

    // forward DIF, first stage reads global directly
    {
        float2 a[8];
#pragma unroll
        for (int i = 0; i < 4; i++) a[i] = u2[t + 512 * i];
#pragma unroll
        for (int i = 4; i < 8; i++) a[i] = make_float2(0.f, 0.f);
        fwd_first_stage(z, t, a);
    }
    __syncthreads();
    stage_g<false, 6, true>(z, t); __syncthreads();
    stage_g<false, 3, true>(z, t); __syncthreads();
    stage_g<false, 0, true>(z, t); __syncthreads();

    // pointwise in digit-reversed domain: z -> z2 (no pair hazard)
    const float4* tab = g_Tab + (size_t)h * 4096;
    for (int p = t; p < 4096; p += 512) {
        int q = rev4((4096 - rev4(p)) & 4095);
        float2 Zp = z[sidx(p)];
        float2 Zq = z[sidx(q)];
        float4 tA = tab[p];
        float nx = tA.x * Zp.x - tA.y * Zp.y + tA.z * Zq.x + tA.w * Zq.y;
        float ny = tA.x * Zp.y + tA.y * Zp.x + tA.w * Zq.x - tA.z * Zq.y;
        z2[sidx(p)] = make_float2(nx, ny);
    }
    __syncthreads();

    // inverse DIT (input digit-reversed), final stage in registers
    stage_g<true, 0, false>(z2, t); __syncthreads();
    stage_g<true, 3, false>(z2, t); __syncthreads();
    stage_g<true, 6, false>(z2, t); __syncthreads();

    float2 a[8];
#pragma unroll
    for (int i = 0; i < 8; i++) a[i] = z2[sidx(t + i * 512)];
    if (t) twiddle8(a, 6.283185307179586f * (float)t / 4096.0f);
    radix8<true>(a);

    float dcoef = D[h];
    uint32_t* yh = g_Yhi + ((size_t)(b * Hh + h)) * (Ll / 2);
    uint32_t* yl = g_Ylo + ((size_t)(b * Hh + h)) * (Ll / 2);
    const float INV_SQRT2 = 0.70710678118654752f;
#pragma unroll
    for (int i = 0; i < 4; i++) {
        int n = t + 512 * i;
        float2 uv = u2[n];
        float y0 = a[i].x + dcoef * uv.x;
        float y1 = a[i].y + dcoef * uv.y;
        y0 = 0.5f * y0 * (1.0f + erff(y0 * INV_SQRT2));
        y1 = 0.5f * y1 * (1.0f + erff(y1 * INV_SQRT2));
        __nv_bfloat16 h0 = __float2bfloat16(y0);
        __nv_bfloat16 h1 = __float2bfloat16(y1);
        float r0 = y0 - __bfloat162float(h0);
        float r1 = y1 - __bfloat162float(h1);
        __nv_bfloat16 l0b = __float2bfloat16(r0);
        __nv_bfloat16 l1b = __float2bfloat16(r1);
        yh[n] = (uint32_t)__bfloat16_as_ushort(h0) | ((uint32_t)__bfloat16_as_ushort(h1) << 16);
        yl[n] = (uint32_t)__bfloat16_as_ushort(l0b) | ((uint32_t)__bfloat16_as_ushort(l1b) << 16);
    }
}

// ---------------------------------------------------------------------------
// Kernel C: HMMA bf16 GEMM, 3-term split, 3-stage cp.async pipeline (k=32),
// one __syncthreads per iteration. CTA 128x128, 8 warps (64x32 each).
// ---------------------------------------------------------------------------
#define HC 32
#define NHC 16
#define A_ST 80
// per-stage: Ahi 10240 | Alo 10240 | Bhi 8192 | Blo 8192 = 36864
#define ST_SZ 36864
#define GEMM_SMEM (3 * ST_SZ)   // 110592

__device__ __forceinline__ uint32_t smem_u32(const void* p) {
    uint32_t a;
    asm("{ .reg .u64 t; cvta.to.shared.u64 t, %1; cvt.u32.u64 %0, t; }" : "=r"(a) : "l"(p));
    return a;
}
__device__ __forceinline__ void cpa16(uint32_t dst, const void* src) {
    asm volatile("cp.async.cg.shared.global [%0], [%1], 16;" :: "r"(dst), "l"(src));
}
__device__ __forceinline__ void ldsm4(uint32_t r[4], uint32_t addr) {
    asm volatile("ldmatrix.sync.aligned.m8n8.x4.shared.b16 {%0,%1,%2,%3}, [%4];"
                 : "=r"(r[0]), "=r"(r[1]), "=r"(r[2]), "=r"(r[3]) : "r"(addr));
}
__device__ __forceinline__ void ldsm4t(uint32_t r[4], uint32_t addr) {
    asm volatile("ldmatrix.sync.aligned.m8n8.x4.trans.shared.b16 {%0,%1,%2,%3}, [%4];"
                 : "=r"(r[0]), "=r"(r[1]), "=r"(r[2]), "=r"(r[3]) : "r"(addr));
}
__device__ __forceinline__ void mma16816(float c[4], const uint32_t a[4], const uint32_t b[2]) {
    asm volatile(
        "mma.sync.aligned.m16n8k16.row.col.f32.bf16.bf16.f32 "
        "{%0,%1,%2,%3}, {%4,%5,%6,%7}, {%8,%9}, {%0,%1,%2,%3};"
        : "+f"(c[0]), "+f"(c[1]), "+f"(c[2]), "+f"(c[3])
        : "r"(a[0]), "r"(a[1]), "r"(a[2]), "r"(a[3]), "r"(b[0]), "r"(b[1]));
}
__device__ __forceinline__ float silu_f(float x) { return x / (1.0f + __expf(-x)); }
__device__ __forceinline__ int bswz(int k, int cb) { return (cb & 8) | ((cb ^ k) & 7); }

__global__ __launch_bounds__(256, 2) void gemm_silu_kernel(const float* __restrict__ bias,
                                                           float* __restrict__ out) {
    extern __shared__ char smem[];
    uint32_t sb = smem_u32(smem);
    int tid = threadIdx.x;
    int wid = tid >> 5;
    int lane = tid & 31;

    int v0 = blockIdx.x * 128;           // vt fastest -> 4 CTAs share B tile in L2
    int l0 = blockIdx.y * 128;
    int b  = blockIdx.z;

    int wm = wid & 1;
    int wn = wid >> 1;

    const __nv_bfloat16* Yh = (const __nv_bfloat16*)g_Yhi;
    const __nv_bfloat16* Yl = (const __nv_bfloat16*)g_Ylo;
    const __nv_bfloat16* Wh = (const __nv_bfloat16*)g_Whi;
    const __nv_bfloat16* Wl = (const __nv_bfloat16*)g_Wlo;

    float acc[4][4][4];
#pragma unroll
    for (int i = 0; i < 4; i++)
#pragma unroll
        for (int j = 0; j < 4; j++)
#pragma unroll
            for (int q = 0; q < 4; q++) acc[i][j][q] = 0.f;

    int ar  = tid >> 2;
    int abk = tid & 3;
    int bk  = tid >> 4;
    int bcb = tid & 15;

    auto load_hc = [&](int hc, int s) {
        int k0 = hc * HC;
        uint32_t base = sb + s * ST_SZ;
#pragma unroll
        for (int g = 0; g < 2; g++) {
            int r = ar + g * 64;
            size_t ga = (size_t)(v0 + r) * Hh + k0 + abk * 8;
            uint32_t da = base + r * A_ST + abk * 16;
            cpa16(da,         Wh + ga);
            cpa16(da + 10240, Wl + ga);
        }
#pragma unroll
        for (int g = 0; g < 2; g++) {
            int k = bk + g * 16;
            size_t ge = ((size_t)(b * Hh) + k0 + k) * Ll + l0 + bcb * 8;
            uint32_t db = base + 20480 + k * 256 + bswz(k, bcb) * 16;
            cpa16(db,        Yh + ge);
            cpa16(db + 8192, Yl + ge);
        }
    };

    load_hc(0, 0);
    asm volatile("cp.async.commit_group;" ::: "memory");
    load_hc(1, 1);
    asm volatile("cp.async.commit_group;" ::: "memory");

    for (int hc = 0; hc < NHC; hc++) {
        if (hc < NHC - 1) {
            asm volatile("cp.async.wait_group 1;" ::: "memory");
        } else {
            asm volatile("cp.async.wait_group 0;" ::: "memory");
        }
        __syncthreads();    // data for hc visible; stage (hc+2)%3 free (readers of hc-1 done)
        if (hc + 2 < NHC) {
            load_hc(hc + 2, (hc + 2) % 3);
            asm volatile("cp.async.commit_group;" ::: "memory");
        }

        uint32_t abase = sb + (hc % 3) * ST_SZ;
        uint32_t bbase = abase + 20480;
#pragma unroll
        for (int ks = 0; ks < 2; ks++) {
            uint32_t bh[2][4], bl[2][4];
#pragma unroll
            for (int g = 0; g < 2; g++) {
                int krow = ks * 16 + (lane & 15);
                int cb = wn * 4 + g * 2 + (lane >> 4);
                uint32_t baddr = bbase + krow * 256 + bswz(krow, cb) * 16;
                ldsm4t(bh[g], baddr);
                ldsm4t(bl[g], baddr + 8192);
            }
#pragma unroll
            for (int mt = 0; mt < 4; mt++) {
                int arow = wm * 64 + mt * 16 + (lane & 15);
                uint32_t aaddr = abase + arow * A_ST + ks * 32 + (lane >> 4) * 16;
                uint32_t ahf[4], alf[4];
                ldsm4(ahf, aaddr);
                ldsm4(alf, aaddr + 10240);
#pragma unroll
                for (int nt = 0; nt < 4; nt++) {
                    const uint32_t* bhx = &bh[nt >> 1][(nt & 1) * 2];
                    const uint32_t* blx = &bl[nt >> 1][(nt & 1) * 2];
                    mma16816(acc[mt][nt], ahf, bhx);
                    mma16816(acc[mt][nt], ahf, blx);
                    mma16816(acc[mt][nt], alf, bhx);
                }
            }
        }
    }

    __syncthreads();
    int g = lane >> 2;
    int cq = (lane & 3) * 2;
#pragma unroll
    for (int mt = 0; mt < 4; mt++) {
        int vbase = v0 + wm * 64 + mt * 16 + g;
        float bv0 = bias[vbase];
        float bv1 = bias[vbase + 8];
        float* row0 = out + ((size_t)(b * Hh) + vbase) * Ll;
        float* row1 = row0 + 8 * Ll;
#pragma unroll
        for (int nt = 0; nt < 4; nt++) {
            int lc = l0 + wn * 32 + nt * 8 + cq;
            float2 o0, o1;
            o0.x = silu_f(acc[mt][nt][0] + bv0);
            o0.y = silu_f(acc[mt][nt][1] + bv0);
            o1.x = silu_f(acc[mt][nt][2] + bv1);
            o1.y = silu_f(acc[mt][nt][3] + bv1);
            *(float2*)(row0 + lc) = o0;
            *(float2*)(row1 + lc) = o1;
        }
    }
}

extern "C" void kernel_launch(void* const* d_in, const int* in_sizes, int n_in,
                              void* d_out, int out_size) {
    const float* u    = (const float*)d_in[0];   // (16, 512, 4096)
    const float* kern = (const float*)d_in[1];   // (1, 512, 4096)
    const float* D    = (const float*)d_in[2];   // (1, 512)
    const float* Wout = (const float*)d_in[3];   // (512, 512)
    const float* bout = (const float*)d_in[4];   // (512,)
    float* out = (float*)d_out;                  // (16, 512, 4096)

    cudaFuncSetAttribute(gemm_silu_kernel, cudaFuncAttributeMaxDynamicSharedMemorySize, GEMM_SMEM);
    cudaFuncSetAttribute(conv_kernel, cudaFuncAttributeMaxDynamicSharedMemorySize, CONV_SMEM);

    build_kf_kernel<<<Hh, 512>>>(kern);
    split_w_kernel<<<256, 256>>>(Wout);
    conv_kernel<<<dim3(Hh, Bb), 512, CONV_SMEM>>>(u, D);
    gemm_silu_kernel<<<dim3(4, 32, 16), 256, GEMM_SMEM>>>(bout, out);
}